// round 9
// baseline (speedup 1.0000x reference)
#include <cuda_runtime.h>

// ---------------------------------------------------------------------------
// Persistent-grid LSTM, 512 threads, warp-specialized:
//   warps 0-7  (compute): phase-A GEMV (16 phases/k, parity+combine), reduce,
//                         gates, h publish.
//   warps 8-15 (fill):    FF head, flag publish, S_in, peer-flag wait, peer h
//                         fill, z finalize -- overlapped with compute.
// Ring slot order: [S_in 0..16][own 17..48][peer ring-dist p at 17+32p].
// ---------------------------------------------------------------------------

namespace {
constexpr int Bb   = 256;
constexpr int Tt   = 200;
constexpr int Fd   = 16;
constexpr int Hh   = 256;
constexpr int NBLK = 128;
constexpr int BG   = 16;
constexpr int HCn  = 32;
constexpr int FWD  = 64;
constexpr int THREADS = 512;
constexpr int CTH  = 256;        // compute threads
constexpr int SLOTS = 280;
constexpr int SPW   = 35;        // slots per compute warp (mod-8 stripes)

constexpr int GP_B  = 576;
constexpr int GP_KQ = 16 * GP_B;

constexpr int OFF_WS    = 0;         // 280*512 = 143360
constexpr int OFF_HST   = 143360;    // 280*80  =  22400
constexpr int OFF_GP    = 165760;    // 4*9216  =  36864
constexpr int OFF_W1KT  = 202624;    //            8192
constexpr int OFF_FFOWN = 210816;    // 16*64 f32  4096
constexpr int OFF_CARR  = 214912;    //            2048
constexpr int OFF_HLOC  = 216960;    //            2048
constexpr int OFF_BSL   = 219008;    //             512
constexpr int OFF_W17   = 219520;    //             512
constexpr int OFF_B1F   = 220032;    //             256
constexpr int OFF_W2F   = 220288;    //             256
constexpr int OFF_ZLOC  = 220544;    //              64
constexpr int OFF_B2    = 220608;
constexpr int OFF_TOK   = 220612;
constexpr int SMEM_BYTES = 220672;

constexpr int OUT_H = Bb * Tt;
constexpr int OUT_C = OUT_H + Bb * Hh;
}

__device__ unsigned g_gflag[16][8][32];
__device__ float    g_hpub[2][16][8][BG * HCn];
__device__ float    g_ff  [2][16][8][BG * FWD];

typedef unsigned long long u64;

__device__ __forceinline__ u64 fma2(u64 a, u64 b, u64 c) {
    u64 d;
    asm("fma.rn.f32x2 %0, %1, %2, %3;" : "=l"(d) : "l"(a), "l"(b), "l"(c));
    return d;
}
__device__ __forceinline__ u64 add2(u64 a, u64 b) {
    u64 d;
    asm("add.rn.f32x2 %0, %1, %2;" : "=l"(d) : "l"(a), "l"(b));
    return d;
}
__device__ __forceinline__ u64 dup2(float x) {
    u64 d;
    asm("mov.b64 %0, {%1, %1};" : "=l"(d) : "f"(x));
    return d;
}
__device__ __forceinline__ float tanha(float x) {
    float y;
    asm("tanh.approx.f32 %0, %1;" : "=f"(y) : "f"(x));
    return y;
}
__device__ __forceinline__ float siga(float x) {
    return fmaf(tanha(x * 0.5f), 0.5f, 0.5f);
}
__device__ __forceinline__ unsigned ld_acq(const unsigned* p) {
    unsigned v;
    asm volatile("ld.acquire.gpu.global.u32 %0, [%1];" : "=r"(v) : "l"(p) : "memory");
    return v;
}
__device__ __forceinline__ void st_rel(unsigned* p, unsigned v) {
    asm volatile("st.release.gpu.global.u32 [%0], %1;" :: "l"(p), "r"(v) : "memory");
}
#define BARX(id, cnt) asm volatile("bar.sync %0, %1;" :: "r"(id), "r"(cnt) : "memory")

__device__ __forceinline__ void wait_peers(int bg, int hc, unsigned need) {
    bool ok = true;
    #pragma unroll
    for (int p = 1; p < 8; ++p)
        ok &= ((int)(ld_acq(&g_gflag[bg][(hc + p) & 7][0]) - need) >= 0);
    if (ok) return;
    for (;;) {
        __nanosleep(32);
        ok = true;
        #pragma unroll
        for (int p = 1; p < 8; ++p)
            ok &= ((int)(ld_acq(&g_gflag[bg][(hc + p) & 7][0]) - need) >= 0);
        if (ok) return;
    }
}

__global__ void __launch_bounds__(THREADS, 1)
lstm_persistent_kernel(const float* __restrict__ zin,  const float* __restrict__ xin,
                       const float* __restrict__ h0,   const float* __restrict__ Wih,
                       const float* __restrict__ Whh,  const float* __restrict__ bias,
                       const float* __restrict__ W1,   const float* __restrict__ b1,
                       const float* __restrict__ W2,   const float* __restrict__ b2,
                       float* __restrict__ out)
{
    extern __shared__ char smem[];
    char*   wsB   = smem + OFF_WS;
    char*   hstB  = smem + OFF_HST;
    char*   gpB   = smem + OFF_GP;
    float*  W1kT  = (float*) (smem + OFF_W1KT);
    float*  ffo   = (float*) (smem + OFF_FFOWN);
    float*  carr  = (float*) (smem + OFF_CARR);
    float*  hloc  = (float*) (smem + OFF_HLOC);
    float2* bsl   = (float2*)(smem + OFF_BSL);
    float*  w17s  = (float*) (smem + OFF_W17);
    float*  b1f   = (float*) (smem + OFF_B1F);
    float*  W2f   = (float*) (smem + OFF_W2F);
    float*  zloc  = (float*) (smem + OFF_ZLOC);
    float*  b2s   = (float*) (smem + OFF_B2);
    unsigned* toks= (unsigned*)(smem + OFF_TOK);

    const int tid = threadIdx.x;
    const int bg  = blockIdx.x >> 3;
    const int hc  = blockIdx.x & 7;
    const int k0  = hc * HCn;

    // ---- prologue --------------------------------------------------------
    if (tid == 0) *toks = g_gflag[bg][hc][0];
    // Ws3: ring slot order, row-pair permuted within slot
    for (int idx = tid; idx < SLOTS * 128; idx += THREADS) {
        int s = idx >> 7, r = idx & 127;
        int p = r >> 1, rl = r & 1, m = p & 3, rr = p >> 2;
        int pos = (m < 2) ? (rr * 4 + m * 2 + rl) : (64 + rr * 4 + (m - 2) * 2 + rl);
        float v = 0.f;
        if (s < 273) {
            int k;
            if (s < 17) k = s;
            else {
                int pp = (s - 17) >> 5, j = (s - 17) & 31;
                int c = (hc + pp) & 7;
                k = 18 + 32 * c + j;
            }
            int grow = ((r >> 5) << 8) + k0 + (r & 31);
            v = (k < 18) ? Wih[grow * 18 + k] : Whh[(grow << 8) + (k - 18)];
        }
        ((float*)(wsB + (size_t)s * 512))[pos] = v;
    }
    for (int idx = tid; idx < SLOTS * 20; idx += THREADS)
        ((float*)hstB)[idx] = 0.f;
    for (int idx = tid; idx < HCn * FWD; idx += THREADS) {
        int j = idx >> 6, f = idx & 63;
        W1kT[idx] = W1[f * Hh + k0 + j];
    }
    if (tid < 128) {
        int r = tid;
        int grow = ((r >> 5) << 8) + k0 + (r & 31);
        w17s[r] = Wih[grow * 18 + 17];
    }
    if (tid < 64) {
        int p = tid;
        int r0i = 2 * p, r1i = r0i + 1;
        float v0 = bias[((r0i >> 5) << 8) + k0 + (r0i & 31)];
        float v1 = bias[((r1i >> 5) << 8) + k0 + (r1i & 31)];
        bsl[p] = make_float2(v0, v1);
        b1f[p] = b1[p];
        W2f[p] = W2[p];
    }
    if (tid == 0) *b2s = b2[0];
    for (int idx = tid; idx < BG * HCn; idx += THREADS) carr[idx] = 0.f;
    if (tid < BG) zloc[tid] = 0.f;
    __syncthreads();
    const unsigned tokbase = *toks;

    const bool isComp = (tid < CTH);

    // compute geometry (tid < 256): warp-pair p4 x parity wsub; tile 8r x 8b
    const int cw = tid >> 5, p4 = cw >> 1, wsub = cw & 1;
    const int lan = tid & 31, ro = lan & 15, bh = lan >> 4;
    const int sbase = p4 + 4 * wsub;               // slot stripe base (mod 8)
    const char* wThr = wsB + ro * 16;
    const char* hThr = hstB + bh * 32;
    char* gpThr = gpB + p4 * GP_KQ + (bh * 8) * GP_B + ro * 32 + (ro >> 2) * 16;
    const int iOwnLo = (17 - sbase + 7) >> 3;      // own slots: s in [17,48]
    const int iOwnHi = (48 - sbase) >> 3;

    // reduce/gate geometry (tid < 256)
    const int gb = tid >> 4, jp = tid & 15, j0 = jp * 2;

    // fill geometry (tid >= 256)
    const int ftid = tid - CTH;
    const int fb = ftid & 15, fsl = ftid >> 4;
    const int pf = ftid & 63, pbq = ftid >> 6;
    const int gbz = ftid >> 4, zlz = ftid & 15;

    // ---- time loop -------------------------------------------------------
    for (int t = 0; t < Tt; ++t) {
        const int pbuf = (t - 1) & 1;
        const int cbuf = t & 1;

        u64 a[4][8];

        if (isComp) {
            #pragma unroll
            for (int m = 0; m < 4; ++m)
                #pragma unroll
                for (int b = 0; b < 8; ++b) a[m][b] = 0ull;
            if (t > 0) {
                // early: own-chunk slots (written by gates(t-1))
                for (int i = iOwnLo; i <= iOwnHi; ++i) {
                    const int s = sbase + 8 * i;
                    ulonglong2 W01 = *(const ulonglong2*)(wThr + (size_t)s * 512);
                    ulonglong2 W23 = *(const ulonglong2*)(wThr + (size_t)s * 512 + 256);
                    float4 H0 = *(const float4*)(hThr + (size_t)s * 80);
                    float4 H1 = *(const float4*)(hThr + (size_t)s * 80 + 16);
                    u64 hd[8];
                    hd[0] = dup2(H0.x); hd[1] = dup2(H0.y);
                    hd[2] = dup2(H0.z); hd[3] = dup2(H0.w);
                    hd[4] = dup2(H1.x); hd[5] = dup2(H1.y);
                    hd[6] = dup2(H1.z); hd[7] = dup2(H1.w);
                    #pragma unroll
                    for (int b = 0; b < 8; ++b) {
                        a[0][b] = fma2(W01.x, hd[b], a[0][b]);
                        a[1][b] = fma2(W01.y, hd[b], a[1][b]);
                        a[2][b] = fma2(W23.x, hd[b], a[2][b]);
                        a[3][b] = fma2(W23.y, hd[b], a[3][b]);
                    }
                }
            }
        } else {
            if (t > 0) {
                // ---- FF(t-1): part[b][f] over own h chunk ----------------
                {
                    float ac0 = 0.f, ac1 = 0.f, ac2 = 0.f, ac3 = 0.f;
                    const float4* h4 = (const float4*)hloc;
                    #pragma unroll
                    for (int jq = 0; jq < 8; ++jq) {
                        float4 hq0 = h4[(pbq * 4 + 0) * 8 + jq];
                        float4 hq1 = h4[(pbq * 4 + 1) * 8 + jq];
                        float4 hq2 = h4[(pbq * 4 + 2) * 8 + jq];
                        float4 hq3 = h4[(pbq * 4 + 3) * 8 + jq];
                        float w0 = W1kT[(jq * 4 + 0) * 64 + pf];
                        float w1 = W1kT[(jq * 4 + 1) * 64 + pf];
                        float w2 = W1kT[(jq * 4 + 2) * 64 + pf];
                        float w3 = W1kT[(jq * 4 + 3) * 64 + pf];
                        ac0 = fmaf(hq0.x, w0, ac0); ac0 = fmaf(hq0.y, w1, ac0);
                        ac0 = fmaf(hq0.z, w2, ac0); ac0 = fmaf(hq0.w, w3, ac0);
                        ac1 = fmaf(hq1.x, w0, ac1); ac1 = fmaf(hq1.y, w1, ac1);
                        ac1 = fmaf(hq1.z, w2, ac1); ac1 = fmaf(hq1.w, w3, ac1);
                        ac2 = fmaf(hq2.x, w0, ac2); ac2 = fmaf(hq2.y, w1, ac2);
                        ac2 = fmaf(hq2.z, w2, ac2); ac2 = fmaf(hq2.w, w3, ac2);
                        ac3 = fmaf(hq3.x, w0, ac3); ac3 = fmaf(hq3.y, w1, ac3);
                        ac3 = fmaf(hq3.z, w2, ac3); ac3 = fmaf(hq3.w, w3, ac3);
                    }
                    float* fp = &g_ff[pbuf][bg][hc][0];
                    fp [(pbq * 4 + 0) * FWD + pf] = ac0;
                    fp [(pbq * 4 + 1) * FWD + pf] = ac1;
                    fp [(pbq * 4 + 2) * FWD + pf] = ac2;
                    fp [(pbq * 4 + 3) * FWD + pf] = ac3;
                    ffo[(pbq * 4 + 0) * FWD + pf] = ac0;
                    ffo[(pbq * 4 + 1) * FWD + pf] = ac1;
                    ffo[(pbq * 4 + 2) * FWD + pf] = ac2;
                    ffo[(pbq * 4 + 3) * FWD + pf] = ac3;
                }
                BARX(2, 256);
                if (ftid == 0) st_rel(&g_gflag[bg][hc][0], tokbase + t);

                // ---- S_in(t) ---------------------------------------------
                {
                    const int bglob = bg * BG + fb;
                    const float* xr = xin + (bglob * Tt + t) * Fd;
                    float v = (fsl == 0) ? zin[bglob * Tt + t] : xr[fsl - 1];
                    *(float*)(hstB + (size_t)fsl * 80 + fb * 4) = v;
                    if (fsl == 0)
                        *(float*)(hstB + (size_t)16 * 80 + fb * 4) = xr[15];
                }

                wait_peers(bg, hc, tokbase + t);

                // ---- peer h fill (ring slots) ----------------------------
                {
                    const int b = ftid >> 4, jj = (ftid & 15) * 2;
                    #pragma unroll
                    for (int p = 1; p < 8; ++p) {
                        int c = (hc + p) & 7;
                        float2 v = __ldcg((const float2*)&g_hpub[pbuf][bg][c][ftid * 2]);
                        int s = 17 + 32 * p + jj;
                        *(float*)(hstB + (size_t)s * 80 + b * 4)       = v.x;
                        *(float*)(hstB + (size_t)(s + 1) * 80 + b * 4) = v.y;
                    }
                }

                // ---- z finalize (t-1) ------------------------------------
                {
                    float4 ov = *(const float4*)(ffo + gbz * FWD + zlz * 4);
                    float a0 = ov.x, a1 = ov.y, a2 = ov.z, a3 = ov.w;
                    #pragma unroll
                    for (int p = 1; p < 8; ++p) {
                        int c = (hc + p) & 7;
                        float4 v = __ldcg((const float4*)&g_ff[pbuf][bg][c][gbz * FWD + zlz * 4]);
                        a0 += v.x; a1 += v.y; a2 += v.z; a3 += v.w;
                    }
                    int f4 = zlz * 4;
                    float s = fmaxf(a0 + b1f[f4], 0.f)     * W2f[f4]
                            + fmaxf(a1 + b1f[f4 + 1], 0.f) * W2f[f4 + 1]
                            + fmaxf(a2 + b1f[f4 + 2], 0.f) * W2f[f4 + 2]
                            + fmaxf(a3 + b1f[f4 + 3], 0.f) * W2f[f4 + 3];
                    s += __shfl_xor_sync(0xffffffffu, s, 1);
                    s += __shfl_xor_sync(0xffffffffu, s, 2);
                    s += __shfl_xor_sync(0xffffffffu, s, 4);
                    s += __shfl_xor_sync(0xffffffffu, s, 8);
                    if (zlz == 0) {
                        float zn = zloc[gbz] + fmaxf(s + *b2s, 0.f);
                        zloc[gbz] = zn;
                        if (hc == 0) out[(bg * BG + gbz) * Tt + (t - 1)] = zn;
                    }
                }
            } else {
                // t = 0: S_in(0) + h0 staging (ring slots)
                {
                    const int bglob = bg * BG + fb;
                    const float* xr = xin + (bglob * Tt) * Fd;
                    float v = (fsl == 0) ? zin[bglob * Tt] : xr[fsl - 1];
                    *(float*)(hstB + (size_t)fsl * 80 + fb * 4) = v;
                    if (fsl == 0)
                        *(float*)(hstB + (size_t)16 * 80 + fb * 4) = xr[15];
                }
                for (int m = 0; m < 16; ++m) {
                    int kk = fsl * 16 + m;
                    int c = kk >> 5, p = (c - hc) & 7;
                    int s = 17 + 32 * p + (kk & 31);
                    *(float*)(hstB + (size_t)s * 80 + fb * 4) =
                        h0[(bg * BG + fb) * Hh + kk];
                }
            }
        }

        __syncthreads();   // FILL_DONE

        if (isComp) {
            // ---- phase A: remaining slots --------------------------------
            auto slotFMA = [&](int s) {
                ulonglong2 W01 = *(const ulonglong2*)(wThr + (size_t)s * 512);
                ulonglong2 W23 = *(const ulonglong2*)(wThr + (size_t)s * 512 + 256);
                float4 H0 = *(const float4*)(hThr + (size_t)s * 80);
                float4 H1 = *(const float4*)(hThr + (size_t)s * 80 + 16);
                u64 hd[8];
                hd[0] = dup2(H0.x); hd[1] = dup2(H0.y);
                hd[2] = dup2(H0.z); hd[3] = dup2(H0.w);
                hd[4] = dup2(H1.x); hd[5] = dup2(H1.y);
                hd[6] = dup2(H1.z); hd[7] = dup2(H1.w);
                #pragma unroll
                for (int b = 0; b < 8; ++b) {
                    a[0][b] = fma2(W01.x, hd[b], a[0][b]);
                    a[1][b] = fma2(W01.y, hd[b], a[1][b]);
                    a[2][b] = fma2(W23.x, hd[b], a[2][b]);
                    a[3][b] = fma2(W23.y, hd[b], a[3][b]);
                }
            };
            if (t > 0) {
                #pragma unroll 2
                for (int i = 0; i < iOwnLo; ++i)      slotFMA(sbase + 8 * i);
                #pragma unroll 2
                for (int i = iOwnHi + 1; i < SPW; ++i) slotFMA(sbase + 8 * i);
            } else {
                #pragma unroll 2
                for (int i = 0; i < SPW; ++i)          slotFMA(sbase + 8 * i);
            }

            // parity store + combine
            if (wsub == 0) {
                #pragma unroll
                for (int b = 0; b < 8; ++b) {
                    ulonglong2* d = (ulonglong2*)(gpThr + b * GP_B);
                    d[0] = make_ulonglong2(a[0][b], a[1][b]);
                    d[1] = make_ulonglong2(a[2][b], a[3][b]);
                }
            }
            BARX(1, 256);
            if (wsub == 1) {
                #pragma unroll
                for (int b = 0; b < 8; ++b) {
                    ulonglong2* d = (ulonglong2*)(gpThr + b * GP_B);
                    ulonglong2 v0 = d[0], v1 = d[1];
                    d[0] = make_ulonglong2(add2(v0.x, a[0][b]), add2(v0.y, a[1][b]));
                    d[1] = make_ulonglong2(add2(v1.x, a[2][b]), add2(v1.y, a[3][b]));
                }
            }
            BARX(1, 256);

            // ---- reduce + bias + z*w17; gates; publish h -----------------
            {
                float2 G[4];
                #pragma unroll
                for (int g = 0; g < 4; ++g) {
                    int pair = g * 16 + jp;
                    size_t off = (size_t)gb * GP_B + pair * 8 + g * 16;
                    float2 s0 = *(const float2*)(gpB + off);
                    float2 s1 = *(const float2*)(gpB + GP_KQ + off);
                    float2 s2 = *(const float2*)(gpB + 2 * GP_KQ + off);
                    float2 s3 = *(const float2*)(gpB + 3 * GP_KQ + off);
                    float2 bv = bsl[pair];
                    G[g].x = s0.x + s1.x + s2.x + s3.x + bv.x;
                    G[g].y = s0.y + s1.y + s2.y + s3.y + bv.y;
                }
                float zp = zloc[gb];
                #pragma unroll
                for (int g = 0; g < 4; ++g) {
                    G[g].x = fmaf(w17s[g * 32 + j0], zp, G[g].x);
                    G[g].y = fmaf(w17s[g * 32 + j0 + 1], zp, G[g].y);
                }
                float2 cc = *(float2*)(carr + gb * 32 + j0);
                float c0 = siga(G[1].x) * cc.x + siga(G[0].x) * tanha(G[2].x);
                float c1 = siga(G[1].y) * cc.y + siga(G[0].y) * tanha(G[2].y);
                float hh0 = siga(G[3].x) * tanha(c0);
                float hh1 = siga(G[3].y) * tanha(c1);
                *(float2*)(carr + gb * 32 + j0) = make_float2(c0, c1);
                *(float2*)(hloc + gb * 32 + j0) = make_float2(hh0, hh1);
                int s = 17 + j0;   // own ring slots for next step
                *(float*)(hstB + (size_t)s * 80 + gb * 4)       = hh0;
                *(float*)(hstB + (size_t)(s + 1) * 80 + gb * 4) = hh1;
                *(float2*)&g_hpub[cbuf][bg][hc][gb * 32 + j0] = make_float2(hh0, hh1);
                if (t == Tt - 1) {
                    int bglob = bg * BG + gb;
                    *(float2*)&out[OUT_H + bglob * Hh + k0 + j0] = make_float2(hh0, hh1);
                    *(float2*)&out[OUT_C + bglob * Hh + k0 + j0] = make_float2(c0, c1);
                }
            }
        }

        __syncthreads();   // GATES_DONE
    }

    // ---- epilogue (fill warps): FF(T-1), flag, final z -------------------
    if (!isComp) {
        const int pbuf = (Tt - 1) & 1;
        {
            float ac0 = 0.f, ac1 = 0.f, ac2 = 0.f, ac3 = 0.f;
            const float4* h4 = (const float4*)hloc;
            #pragma unroll
            for (int jq = 0; jq < 8; ++jq) {
                float4 hq0 = h4[(pbq * 4 + 0) * 8 + jq];
                float4 hq1 = h4[(pbq * 4 + 1) * 8 + jq];
                float4 hq2 = h4[(pbq * 4 + 2) * 8 + jq];
                float4 hq3 = h4[(pbq * 4 + 3) * 8 + jq];
                float w0 = W1kT[(jq * 4 + 0) * 64 + pf];
                float w1 = W1kT[(jq * 4 + 1) * 64 + pf];
                float w2 = W1kT[(jq * 4 + 2) * 64 + pf];
                float w3 = W1kT[(jq * 4 + 3) * 64 + pf];
                ac0 = fmaf(hq0.x, w0, ac0); ac0 = fmaf(hq0.y, w1, ac0);
                ac0 = fmaf(hq0.z, w2, ac0); ac0 = fmaf(hq0.w, w3, ac0);
                ac1 = fmaf(hq1.x, w0, ac1); ac1 = fmaf(hq1.y, w1, ac1);
                ac1 = fmaf(hq1.z, w2, ac1); ac1 = fmaf(hq1.w, w3, ac1);
                ac2 = fmaf(hq2.x, w0, ac2); ac2 = fmaf(hq2.y, w1, ac2);
                ac2 = fmaf(hq2.z, w2, ac2); ac2 = fmaf(hq2.w, w3, ac2);
                ac3 = fmaf(hq3.x, w0, ac3); ac3 = fmaf(hq3.y, w1, ac3);
                ac3 = fmaf(hq3.z, w2, ac3); ac3 = fmaf(hq3.w, w3, ac3);
            }
            float* fp = &g_ff[pbuf][bg][hc][0];
            fp [(pbq * 4 + 0) * FWD + pf] = ac0;
            fp [(pbq * 4 + 1) * FWD + pf] = ac1;
            fp [(pbq * 4 + 2) * FWD + pf] = ac2;
            fp [(pbq * 4 + 3) * FWD + pf] = ac3;
            ffo[(pbq * 4 + 0) * FWD + pf] = ac0;
            ffo[(pbq * 4 + 1) * FWD + pf] = ac1;
            ffo[(pbq * 4 + 2) * FWD + pf] = ac2;
            ffo[(pbq * 4 + 3) * FWD + pf] = ac3;
        }
        BARX(2, 256);
        if (ftid == 0) st_rel(&g_gflag[bg][hc][0], tokbase + Tt);

        if (hc == 0) {
            wait_peers(bg, hc, tokbase + Tt);
            float4 ov = *(const float4*)(ffo + gbz * FWD + zlz * 4);
            float a0 = ov.x, a1 = ov.y, a2 = ov.z, a3 = ov.w;
            #pragma unroll
            for (int p = 1; p < 8; ++p) {
                int c = p & 7;
                float4 v = __ldcg((const float4*)&g_ff[pbuf][bg][c][gbz * FWD + zlz * 4]);
                a0 += v.x; a1 += v.y; a2 += v.z; a3 += v.w;
            }
            int f4 = zlz * 4;
            float s = fmaxf(a0 + b1f[f4], 0.f)     * W2f[f4]
                    + fmaxf(a1 + b1f[f4 + 1], 0.f) * W2f[f4 + 1]
                    + fmaxf(a2 + b1f[f4 + 2], 0.f) * W2f[f4 + 2]
                    + fmaxf(a3 + b1f[f4 + 3], 0.f) * W2f[f4 + 3];
            s += __shfl_xor_sync(0xffffffffu, s, 1);
            s += __shfl_xor_sync(0xffffffffu, s, 2);
            s += __shfl_xor_sync(0xffffffffu, s, 4);
            s += __shfl_xor_sync(0xffffffffu, s, 8);
            if (zlz == 0) {
                float zn = zloc[gbz] + fmaxf(s + *b2s, 0.f);
                out[(bg * BG + gbz) * Tt + (Tt - 1)] = zn;
            }
        }
    }
}

extern "C" void kernel_launch(void* const* d_in, const int* in_sizes, int n_in,
                              void* d_out, int out_size) {
    const float* z   = (const float*)d_in[0];
    const float* x   = (const float*)d_in[1];
    const float* h0  = (const float*)d_in[2];
    const float* Wih = (const float*)d_in[3];
    const float* Whh = (const float*)d_in[4];
    const float* b   = (const float*)d_in[5];
    const float* W1  = (const float*)d_in[6];
    const float* b1  = (const float*)d_in[7];
    const float* W2  = (const float*)d_in[8];
    const float* b2  = (const float*)d_in[9];
    float* out = (float*)d_out;

    cudaFuncSetAttribute(lstm_persistent_kernel,
                         cudaFuncAttributeMaxDynamicSharedMemorySize, SMEM_BYTES);
    lstm_persistent_kernel<<<NBLK, THREADS, SMEM_BYTES>>>(
        z, x, h0, Wih, Whh, b, W1, b1, W2, b2, out);
}

// round 10
// speedup vs baseline: 1.0440x; 1.0440x over previous
#include <cuda_runtime.h>

// ---------------------------------------------------------------------------
// Persistent-grid LSTM, 256 threads. Phase A at crossbar floor (16 phases/k,
// parity warp pairs + vectorized combine). Ring slot layout (own chunk at
// slots 17..48) enables early own-FMA that hides the step's entire batched
// LDG window (ff partials, peer h, S_in). g_hpub transposed [j][b] for
// coalesced peer fill. MUFU.TANH gates. Dataflow flags, no grid barriers.
// ---------------------------------------------------------------------------

namespace {
constexpr int Bb   = 256;
constexpr int Tt   = 200;
constexpr int Fd   = 16;
constexpr int Hh   = 256;
constexpr int NBLK = 128;
constexpr int BG   = 16;
constexpr int HCn  = 32;
constexpr int FWD  = 64;
constexpr int THREADS = 256;
constexpr int SLOTS = 280;       // ring: 0..16 S_in; 17..48 own; 49..272 peers
constexpr int SPW   = 35;        // slots per warp (mod-8 stripes)

constexpr int GP_B  = 576;
constexpr int GP_KQ = 16 * GP_B;

constexpr int OFF_WS   = 0;         // 280*512 = 143360
constexpr int OFF_HST  = 143360;    // 280*80  =  22400
constexpr int OFF_GP   = 165760;    // 4*9216  =  36864
constexpr int OFF_W1KT = 202624;    //             8192
constexpr int OFF_CARR = 210816;    //             2048
constexpr int OFF_HLOC = 212864;    //             2048
constexpr int OFF_BSL  = 214912;    //              512
constexpr int OFF_W17  = 215424;    //              512
constexpr int OFF_B1F  = 215936;    //              256
constexpr int OFF_W2F  = 216192;    //              256
constexpr int OFF_ZLOC = 216448;    //               64
constexpr int OFF_B2   = 216512;
constexpr int OFF_TOK  = 216516;
constexpr int SMEM_BYTES = 216576;

constexpr int OUT_H = Bb * Tt;
constexpr int OUT_C = OUT_H + Bb * Hh;
}

__device__ unsigned g_gflag[16][8][32];
__device__ float    g_hpub[2][16][8][HCn * BG];   // TRANSPOSED: [j*16 + b]
__device__ float    g_ff  [2][16][8][BG * FWD];   // [b*64 + f]

typedef unsigned long long u64;

__device__ __forceinline__ u64 fma2(u64 a, u64 b, u64 c) {
    u64 d;
    asm("fma.rn.f32x2 %0, %1, %2, %3;" : "=l"(d) : "l"(a), "l"(b), "l"(c));
    return d;
}
__device__ __forceinline__ u64 add2(u64 a, u64 b) {
    u64 d;
    asm("add.rn.f32x2 %0, %1, %2;" : "=l"(d) : "l"(a), "l"(b));
    return d;
}
__device__ __forceinline__ u64 dup2(float x) {
    u64 d;
    asm("mov.b64 %0, {%1, %1};" : "=l"(d) : "f"(x));
    return d;
}
__device__ __forceinline__ float tanha(float x) {
    float y;
    asm("tanh.approx.f32 %0, %1;" : "=f"(y) : "f"(x));
    return y;
}
__device__ __forceinline__ float siga(float x) {
    return fmaf(tanha(x * 0.5f), 0.5f, 0.5f);
}
__device__ __forceinline__ unsigned ld_acq(const unsigned* p) {
    unsigned v;
    asm volatile("ld.acquire.gpu.global.u32 %0, [%1];" : "=r"(v) : "l"(p) : "memory");
    return v;
}
__device__ __forceinline__ void st_rel(unsigned* p, unsigned v) {
    asm volatile("st.release.gpu.global.u32 [%0], %1;" :: "l"(p), "r"(v) : "memory");
}
__device__ __forceinline__ void wait_peers(int bg, int hc, unsigned need) {
    bool ok = true;
    #pragma unroll
    for (int p = 1; p < 8; ++p)
        ok &= ((int)(ld_acq(&g_gflag[bg][(hc + p) & 7][0]) - need) >= 0);
    if (ok) return;
    for (;;) {
        __nanosleep(32);
        ok = true;
        #pragma unroll
        for (int p = 1; p < 8; ++p)
            ok &= ((int)(ld_acq(&g_gflag[bg][(hc + p) & 7][0]) - need) >= 0);
        if (ok) return;
    }
}

__global__ void __launch_bounds__(THREADS, 1)
lstm_persistent_kernel(const float* __restrict__ zin,  const float* __restrict__ xin,
                       const float* __restrict__ h0,   const float* __restrict__ Wih,
                       const float* __restrict__ Whh,  const float* __restrict__ bias,
                       const float* __restrict__ W1,   const float* __restrict__ b1,
                       const float* __restrict__ W2,   const float* __restrict__ b2,
                       float* __restrict__ out)
{
    extern __shared__ char smem[];
    char*   wsB   = smem + OFF_WS;
    char*   hstB  = smem + OFF_HST;
    char*   gpB   = smem + OFF_GP;
    float*  W1kT  = (float*) (smem + OFF_W1KT);
    float*  carr  = (float*) (smem + OFF_CARR);
    float*  hloc  = (float*) (smem + OFF_HLOC);
    float2* bsl   = (float2*)(smem + OFF_BSL);
    float*  w17s  = (float*) (smem + OFF_W17);
    float*  b1f   = (float*) (smem + OFF_B1F);
    float*  W2f   = (float*) (smem + OFF_W2F);
    float*  zloc  = (float*) (smem + OFF_ZLOC);
    float*  b2s   = (float*) (smem + OFF_B2);
    unsigned* toks= (unsigned*)(smem + OFF_TOK);

    const int tid = threadIdx.x;
    const int bg  = blockIdx.x >> 3;
    const int hc  = blockIdx.x & 7;
    const int k0  = hc * HCn;

    // ---- prologue --------------------------------------------------------
    if (tid == 0) *toks = g_gflag[bg][hc][0];
    // Ws3: ring slot order, row-pair permuted within slot
    for (int idx = tid; idx < SLOTS * 128; idx += THREADS) {
        int s = idx >> 7, r = idx & 127;
        int p = r >> 1, rl = r & 1, m = p & 3, rr = p >> 2;
        int pos = (m < 2) ? (rr * 4 + m * 2 + rl) : (64 + rr * 4 + (m - 2) * 2 + rl);
        float v = 0.f;
        if (s < 273) {
            int k;
            if (s < 17) k = s;
            else {
                int pp = (s - 17) >> 5, j = (s - 17) & 31;
                int c = (hc + pp) & 7;
                k = 18 + 32 * c + j;
            }
            int grow = ((r >> 5) << 8) + k0 + (r & 31);
            v = (k < 18) ? Wih[grow * 18 + k] : Whh[(grow << 8) + (k - 18)];
        }
        ((float*)(wsB + (size_t)s * 512))[pos] = v;
    }
    for (int idx = tid; idx < SLOTS * 20; idx += THREADS)
        ((float*)hstB)[idx] = 0.f;
    for (int idx = tid; idx < HCn * FWD; idx += THREADS) {
        int j = idx >> 6, f = idx & 63;
        W1kT[idx] = W1[f * Hh + k0 + j];
    }
    if (tid < 128) {
        int r = tid;
        int grow = ((r >> 5) << 8) + k0 + (r & 31);
        w17s[r] = Wih[grow * 18 + 17];
    }
    if (tid < 64) {
        int p = tid;
        int r0i = 2 * p, r1i = r0i + 1;
        float v0 = bias[((r0i >> 5) << 8) + k0 + (r0i & 31)];
        float v1 = bias[((r1i >> 5) << 8) + k0 + (r1i & 31)];
        bsl[p] = make_float2(v0, v1);
        b1f[p] = b1[p];
        W2f[p] = W2[p];
    }
    if (tid == 0) *b2s = b2[0];
    for (int idx = tid; idx < BG * HCn; idx += THREADS) carr[idx] = 0.f;
    if (tid < BG) zloc[tid] = 0.f;
    __syncthreads();
    const unsigned tokbase = *toks;

    // phase-A geometry: warp pair per k-quarter, slot-stripe mod 8
    const int warp = tid >> 5, kq = warp >> 1, wsub = warp & 1;
    const int lan = tid & 31, ro = lan & 15, bh = lan >> 4;
    const int sbase = kq + 4 * wsub;               // stripe residue 0..7
    const char* wThr = wsB + ro * 16;
    const char* hThr = hstB + bh * 32;
    char* gpThr = gpB + kq * GP_KQ + (bh * 8) * GP_B + ro * 32 + (ro >> 2) * 16;
    const int iOwnLo = (17 - sbase + 7) >> 3;      // own slots in [17,48]
    const int iOwnHi = (48 - sbase) >> 3;

    // reduce/gate geometry
    const int gb = tid >> 4, jp = tid & 15, j0 = jp * 2;
    // FF geometry
    const int pf = tid & 63, pbq = tid >> 6;
    // S_in / peer-fill geometry
    const int fb = tid & 15, fsl = tid >> 4;

    // ---- time loop -------------------------------------------------------
    for (int t = 0; t < Tt; ++t) {
        const int pbuf = (t - 1) & 1;
        const int cbuf = t & 1;

        u64 a[4][8];
        #pragma unroll
        for (int m = 0; m < 4; ++m)
            #pragma unroll
            for (int b = 0; b < 8; ++b) a[m][b] = 0ull;

        auto slotFMA = [&](int s) {
            ulonglong2 W01 = *(const ulonglong2*)(wThr + (size_t)s * 512);
            ulonglong2 W23 = *(const ulonglong2*)(wThr + (size_t)s * 512 + 256);
            float4 H0 = *(const float4*)(hThr + (size_t)s * 80);
            float4 H1 = *(const float4*)(hThr + (size_t)s * 80 + 16);
            u64 hd[8];
            hd[0] = dup2(H0.x); hd[1] = dup2(H0.y);
            hd[2] = dup2(H0.z); hd[3] = dup2(H0.w);
            hd[4] = dup2(H1.x); hd[5] = dup2(H1.y);
            hd[6] = dup2(H1.z); hd[7] = dup2(H1.w);
            #pragma unroll
            for (int b = 0; b < 8; ++b) {
                a[0][b] = fma2(W01.x, hd[b], a[0][b]);
                a[1][b] = fma2(W01.y, hd[b], a[1][b]);
                a[2][b] = fma2(W23.x, hd[b], a[2][b]);
                a[3][b] = fma2(W23.y, hd[b], a[3][b]);
            }
        };

        if (t > 0) {
            wait_peers(bg, hc, tokbase + t);

            // ---- one batched LDG window (MLP) ----------------------------
            float4 ffv[8];
            #pragma unroll
            for (int c = 0; c < 8; ++c)
                ffv[c] = __ldcg((const float4*)&g_ff[pbuf][bg][c][gb * FWD + jp * 4]);
            float phv[14];
            #pragma unroll
            for (int i = 0; i < 14; ++i) {
                int sg = i * 16 + fsl;                      // 0..223
                int cc = (hc + 1 + (sg >> 5)) & 7;
                phv[i] = __ldcg(&g_hpub[pbuf][bg][cc][(sg & 31) * 16 + fb]);
            }
            const int bglob_f = bg * BG + fb;
            const float* xr = xin + (bglob_f * Tt + t) * Fd;
            float vin1 = (fsl == 0) ? zin[bglob_f * Tt + t] : xr[fsl - 1];
            float vin2 = (fsl == 0) ? xr[15] : 0.f;

            // ---- own-chunk FMA hides the load window ---------------------
            #pragma unroll
            for (int i = 0; i < 8; ++i) {
                int ii = iOwnLo + i;
                if (ii <= iOwnHi) slotFMA(sbase + 8 * ii);
            }

            // ---- consume: z finalize -------------------------------------
            {
                float a0 = 0.f, a1 = 0.f, a2 = 0.f, a3 = 0.f;
                #pragma unroll
                for (int c = 0; c < 8; ++c) {
                    a0 += ffv[c].x; a1 += ffv[c].y;
                    a2 += ffv[c].z; a3 += ffv[c].w;
                }
                int f4 = jp * 4;
                float s = fmaxf(a0 + b1f[f4], 0.f)     * W2f[f4]
                        + fmaxf(a1 + b1f[f4 + 1], 0.f) * W2f[f4 + 1]
                        + fmaxf(a2 + b1f[f4 + 2], 0.f) * W2f[f4 + 2]
                        + fmaxf(a3 + b1f[f4 + 3], 0.f) * W2f[f4 + 3];
                s += __shfl_xor_sync(0xffffffffu, s, 1);
                s += __shfl_xor_sync(0xffffffffu, s, 2);
                s += __shfl_xor_sync(0xffffffffu, s, 4);
                s += __shfl_xor_sync(0xffffffffu, s, 8);
                if (jp == 0) {
                    float zn = zloc[gb] + fmaxf(s + *b2s, 0.f);
                    zloc[gb] = zn;
                    if (hc == 0) out[(bg * BG + gb) * Tt + (t - 1)] = zn;
                }
            }
            // ---- consume: S_in + peer h into hst -------------------------
            *(float*)(hstB + (size_t)fsl * 80 + fb * 4) = vin1;
            if (fsl == 0)
                *(float*)(hstB + (size_t)16 * 80 + fb * 4) = vin2;
            #pragma unroll
            for (int i = 0; i < 14; ++i) {
                int s = 49 + i * 16 + fsl;
                *(float*)(hstB + (size_t)s * 80 + fb * 4) = phv[i];
            }
        } else {
            // t = 0: S_in + h0 staging (ring slots)
            const int bglob_f = bg * BG + fb;
            const float* xr = xin + (bglob_f * Tt) * Fd;
            float vin1 = (fsl == 0) ? zin[bglob_f * Tt] : xr[fsl - 1];
            *(float*)(hstB + (size_t)fsl * 80 + fb * 4) = vin1;
            if (fsl == 0)
                *(float*)(hstB + (size_t)16 * 80 + fb * 4) = xr[15];
            for (int m = 0; m < 16; ++m) {
                int kk = fsl * 16 + m;
                int c = kk >> 5, p = (c - hc) & 7;
                int s = 17 + 32 * p + (kk & 31);
                *(float*)(hstB + (size_t)s * 80 + fb * 4) =
                    h0[bglob_f * Hh + kk];
            }
        }

        __syncthreads();   // hst + zloc ready

        // ---- phase A: remaining slots ------------------------------------
        if (t > 0) {
            #pragma unroll 2
            for (int i = 0; i < iOwnLo; ++i)       slotFMA(sbase + 8 * i);
            #pragma unroll 2
            for (int i = iOwnHi + 1; i < SPW; ++i) slotFMA(sbase + 8 * i);
        } else {
            #pragma unroll 2
            for (int i = 0; i < SPW; ++i)          slotFMA(sbase + 8 * i);
        }

        // parity store + combine
        if (wsub == 0) {
            #pragma unroll
            for (int b = 0; b < 8; ++b) {
                ulonglong2* d = (ulonglong2*)(gpThr + b * GP_B);
                d[0] = make_ulonglong2(a[0][b], a[1][b]);
                d[1] = make_ulonglong2(a[2][b], a[3][b]);
            }
        }
        __syncthreads();
        if (wsub == 1) {
            #pragma unroll
            for (int b = 0; b < 8; ++b) {
                ulonglong2* d = (ulonglong2*)(gpThr + b * GP_B);
                ulonglong2 v0 = d[0], v1 = d[1];
                d[0] = make_ulonglong2(add2(v0.x, a[0][b]), add2(v0.y, a[1][b]));
                d[1] = make_ulonglong2(add2(v1.x, a[2][b]), add2(v1.y, a[3][b]));
            }
        }
        __syncthreads();

        // ---- reduce + bias + z*w17; gates; publish h ---------------------
        {
            float2 G[4];
            #pragma unroll
            for (int g = 0; g < 4; ++g) {
                int pair = g * 16 + jp;
                size_t off = (size_t)gb * GP_B + pair * 8 + g * 16;
                float2 s0 = *(const float2*)(gpB + off);
                float2 s1 = *(const float2*)(gpB + GP_KQ + off);
                float2 s2 = *(const float2*)(gpB + 2 * GP_KQ + off);
                float2 s3 = *(const float2*)(gpB + 3 * GP_KQ + off);
                float2 bv = bsl[pair];
                G[g].x = s0.x + s1.x + s2.x + s3.x + bv.x;
                G[g].y = s0.y + s1.y + s2.y + s3.y + bv.y;
            }
            float zp = zloc[gb];
            #pragma unroll
            for (int g = 0; g < 4; ++g) {
                G[g].x = fmaf(w17s[g * 32 + j0], zp, G[g].x);
                G[g].y = fmaf(w17s[g * 32 + j0 + 1], zp, G[g].y);
            }
            float2 cc = *(float2*)(carr + gb * 32 + j0);
            float c0 = siga(G[1].x) * cc.x + siga(G[0].x) * tanha(G[2].x);
            float c1 = siga(G[1].y) * cc.y + siga(G[0].y) * tanha(G[2].y);
            float hh0 = siga(G[3].x) * tanha(c0);
            float hh1 = siga(G[3].y) * tanha(c1);
            *(float2*)(carr + gb * 32 + j0) = make_float2(c0, c1);
            *(float2*)(hloc + gb * 32 + j0) = make_float2(hh0, hh1);
            int s = 17 + j0;   // own ring slots for next step
            *(float*)(hstB + (size_t)s * 80 + gb * 4)       = hh0;
            *(float*)(hstB + (size_t)(s + 1) * 80 + gb * 4) = hh1;
            // transposed publish [j][b] (fire-and-forget)
            g_hpub[cbuf][bg][hc][j0 * 16 + gb]       = hh0;
            g_hpub[cbuf][bg][hc][(j0 + 1) * 16 + gb] = hh1;
            if (t == Tt - 1) {
                int bglob = bg * BG + gb;
                *(float2*)&out[OUT_H + bglob * Hh + k0 + j0] = make_float2(hh0, hh1);
                *(float2*)&out[OUT_C + bglob * Hh + k0 + j0] = make_float2(c0, c1);
            }
        }
        __syncthreads();   // hloc ready

        // ---- FF k-partials: part[b][f] = sum_j W1[f][k0+j] h[b][j] -------
        {
            float ac0 = 0.f, ac1 = 0.f, ac2 = 0.f, ac3 = 0.f;
            const float4* h4 = (const float4*)hloc;
            #pragma unroll
            for (int jq = 0; jq < 8; ++jq) {
                float4 hq0 = h4[(pbq * 4 + 0) * 8 + jq];
                float4 hq1 = h4[(pbq * 4 + 1) * 8 + jq];
                float4 hq2 = h4[(pbq * 4 + 2) * 8 + jq];
                float4 hq3 = h4[(pbq * 4 + 3) * 8 + jq];
                float w0 = W1kT[(jq * 4 + 0) * 64 + pf];
                float w1 = W1kT[(jq * 4 + 1) * 64 + pf];
                float w2 = W1kT[(jq * 4 + 2) * 64 + pf];
                float w3 = W1kT[(jq * 4 + 3) * 64 + pf];
                ac0 = fmaf(hq0.x, w0, ac0); ac0 = fmaf(hq0.y, w1, ac0);
                ac0 = fmaf(hq0.z, w2, ac0); ac0 = fmaf(hq0.w, w3, ac0);
                ac1 = fmaf(hq1.x, w0, ac1); ac1 = fmaf(hq1.y, w1, ac1);
                ac1 = fmaf(hq1.z, w2, ac1); ac1 = fmaf(hq1.w, w3, ac1);
                ac2 = fmaf(hq2.x, w0, ac2); ac2 = fmaf(hq2.y, w1, ac2);
                ac2 = fmaf(hq2.z, w2, ac2); ac2 = fmaf(hq2.w, w3, ac2);
                ac3 = fmaf(hq3.x, w0, ac3); ac3 = fmaf(hq3.y, w1, ac3);
                ac3 = fmaf(hq3.z, w2, ac3); ac3 = fmaf(hq3.w, w3, ac3);
            }
            float* fp = &g_ff[cbuf][bg][hc][0];
            fp[(pbq * 4 + 0) * FWD + pf] = ac0;
            fp[(pbq * 4 + 1) * FWD + pf] = ac1;
            fp[(pbq * 4 + 2) * FWD + pf] = ac2;
            fp[(pbq * 4 + 3) * FWD + pf] = ac3;
        }
        __syncthreads();   // publishes complete block-wide
        if (tid == 0) st_rel(&g_gflag[bg][hc][0], tokbase + t + 1);
    }

    // ---- epilogue: finalize z_{T-1} (hc 0 only) --------------------------
    if (hc == 0) {
        wait_peers(bg, hc, tokbase + Tt);
        const int pbuf = (Tt - 1) & 1;
        float a0 = 0.f, a1 = 0.f, a2 = 0.f, a3 = 0.f;
        #pragma unroll
        for (int c = 0; c < 8; ++c) {
            float4 v = __ldcg((const float4*)&g_ff[pbuf][bg][c][gb * FWD + jp * 4]);
            a0 += v.x; a1 += v.y; a2 += v.z; a3 += v.w;
        }
        int f4 = jp * 4;
        float s = fmaxf(a0 + b1f[f4], 0.f)     * W2f[f4]
                + fmaxf(a1 + b1f[f4 + 1], 0.f) * W2f[f4 + 1]
                + fmaxf(a2 + b1f[f4 + 2], 0.f) * W2f[f4 + 2]
                + fmaxf(a3 + b1f[f4 + 3], 0.f) * W2f[f4 + 3];
        s += __shfl_xor_sync(0xffffffffu, s, 1);
        s += __shfl_xor_sync(0xffffffffu, s, 2);
        s += __shfl_xor_sync(0xffffffffu, s, 4);
        s += __shfl_xor_sync(0xffffffffu, s, 8);
        if (jp == 0) {
            float zn = zloc[gb] + fmaxf(s + *b2s, 0.f);
            out[(bg * BG + gb) * Tt + (Tt - 1)] = zn;
        }
    }
}

extern "C" void kernel_launch(void* const* d_in, const int* in_sizes, int n_in,
                              void* d_out, int out_size) {
    const float* z   = (const float*)d_in[0];
    const float* x   = (const float*)d_in[1];
    const float* h0  = (const float*)d_in[2];
    const float* Wih = (const float*)d_in[3];
    const float* Whh = (const float*)d_in[4];
    const float* b   = (const float*)d_in[5];
    const float* W1  = (const float*)d_in[6];
    const float* b1  = (const float*)d_in[7];
    const float* W2  = (const float*)d_in[8];
    const float* b2  = (const float*)d_in[9];
    float* out = (float*)d_out;

    cudaFuncSetAttribute(lstm_persistent_kernel,
                         cudaFuncAttributeMaxDynamicSharedMemorySize, SMEM_BYTES);
    lstm_persistent_kernel<<<NBLK, THREADS, SMEM_BYTES>>>(
        z, x, h0, Wih, Whh, b, W1, b1, W2, b2, out);
}

// round 14
// speedup vs baseline: 1.2824x; 1.2283x over previous
#include <cuda_runtime.h>
#include <cuda_bf16.h>

// ---------------------------------------------------------------------------
// Persistent-grid LSTM on HMMA (mma.sync.m16n8k16 bf16, sm_100 baseline PTX).
// 128 blocks = 16 batch groups x 8 hidden chunks, 256 threads.
// One unified GEMM per step: D[192x16] = A[192x288] x B[288x16]:
//   rows 0..127  = gate rows  (Whh | Wih cols 0..16 | 0 | bias)
//   rows 128..191= W1 rows    (W1  | 0 ... | b1)      -> FF head fused, no g_ff
// bf16 hi/lo split: gates 3-term, FF 2-term. z_prev = fp32 rank-1 fixup.
// Inter-block: h published as packed (bf16 hi | lo<<16). Dataflow flags.
// All spin loops BOUNDED (~0.4s) so any protocol failure surfaces as a
// rel_err failure with diagnostics instead of a container-killing hang.
// ---------------------------------------------------------------------------

namespace {
constexpr int Bb = 256, Tt = 200, Fd = 16, Hh = 256;
constexpr int NBLK = 128, BG = 16, HCn = 32, FWD = 64;
constexpr int THREADS = 256;
constexpr int NCH = 18;             // K16 chunks (K = 288)
constexpr int RS  = 592;            // A/B row stride bytes (148 words == 20 mod 32)

constexpr int OFF_AH  = 0;          // 192*592 = 113664
constexpr int OFF_AL  = 113664;     // 128*592 =  75776 -> 189440
constexpr int OFF_BH  = 189440;     // 16*592  =   9472 -> 198912
constexpr int OFF_BL  = 198912;     //             9472 -> 208384
constexpr int OFF_G   = 208384;     // 16*784  =  12544 -> 220928
constexpr int OFF_W17 = 220928;     // 128 f32 =    512 -> 221440
constexpr int OFF_W2F = 221440;     // 64 f32  =    256 -> 221696
constexpr int OFF_CARR= 221696;     // 512 f32 =   2048 -> 223744
constexpr int OFF_ZLOC= 223744;     // 16 f32 (pad 64)  -> 223808
constexpr int OFF_B2  = 223808;
constexpr int OFF_TOK = 223812;
constexpr int SMEM_BYTES = 223872;

constexpr int OUT_H = Bb * Tt, OUT_C = OUT_H + Bb * Hh;
}

__device__ unsigned g_gflag[16][8][32];
__device__ unsigned g_hpub[2][16][8][HCn * BG];   // idx j*16+b, val hi|lo<<16

__device__ __forceinline__ float tanha(float x) {
    float y; asm("tanh.approx.f32 %0, %1;" : "=f"(y) : "f"(x)); return y;
}
__device__ __forceinline__ float siga(float x) {
    return fmaf(tanha(x * 0.5f), 0.5f, 0.5f);
}
__device__ __forceinline__ unsigned ld_acq(const unsigned* p) {
    unsigned v;
    asm volatile("ld.acquire.gpu.global.u32 %0, [%1];" : "=r"(v) : "l"(p) : "memory");
    return v;
}
__device__ __forceinline__ void st_rel(unsigned* p, unsigned v) {
    asm volatile("st.release.gpu.global.u32 [%0], %1;" :: "l"(p), "r"(v) : "memory");
}
// Bounded spin: ~4M passes x ~100ns ~= 0.4 s worst case. Never reached in a
// healthy run (steady-state waits are microseconds); on protocol failure the
// kernel completes with wrong data instead of hanging the container.
__device__ __forceinline__ void wait_peers(int bg, int hc, unsigned need) {
    for (int spin = 0; spin < (1 << 22); ++spin) {
        bool ok = true;
        #pragma unroll
        for (int p = 1; p < 8; ++p)
            ok &= ((int)(ld_acq(&g_gflag[bg][(hc + p) & 7][0]) - need) >= 0);
        if (ok) return;
        __nanosleep(64);
    }
}
__device__ __forceinline__ void mma16816(float& d0, float& d1, float& d2, float& d3,
                                         unsigned a0, unsigned a1, unsigned a2, unsigned a3,
                                         unsigned b0, unsigned b1) {
    asm("mma.sync.aligned.m16n8k16.row.col.f32.bf16.bf16.f32 "
        "{%0,%1,%2,%3}, {%4,%5,%6,%7}, {%8,%9}, {%0,%1,%2,%3};"
        : "+f"(d0), "+f"(d1), "+f"(d2), "+f"(d3)
        : "r"(a0), "r"(a1), "r"(a2), "r"(a3), "r"(b0), "r"(b1));
}
__device__ __forceinline__ unsigned short bsplit(float v, unsigned short& lo) {
    __nv_bfloat16 h = __float2bfloat16(v);
    lo = __bfloat16_as_ushort(__float2bfloat16(v - __bfloat162float(h)));
    return __bfloat16_as_ushort(h);
}

__global__ void __launch_bounds__(THREADS, 1)
lstm_persistent_kernel(const float* __restrict__ zin,  const float* __restrict__ xin,
                       const float* __restrict__ h0,   const float* __restrict__ Wih,
                       const float* __restrict__ Whh,  const float* __restrict__ bias,
                       const float* __restrict__ W1,   const float* __restrict__ b1,
                       const float* __restrict__ W2,   const float* __restrict__ b2,
                       float* __restrict__ out)
{
    extern __shared__ char smem[];
    float* w17s = (float*)(smem + OFF_W17);
    float* W2f  = (float*)(smem + OFF_W2F);
    float* carr = (float*)(smem + OFF_CARR);
    float* zloc = (float*)(smem + OFF_ZLOC);
    float* b2s  = (float*)(smem + OFF_B2);
    unsigned* toks = (unsigned*)(smem + OFF_TOK);

    const int tid = threadIdx.x;
    const int bg  = blockIdx.x >> 3;
    const int hc  = blockIdx.x & 7;
    const int k0  = hc * HCn;

    // ---- prologue --------------------------------------------------------
    if (tid == 0) *toks = g_gflag[bg][hc][0];
    // A matrix (hi + gate-lo), k-order: 0..255 h | 256..272 z_t,x | 273 0 | 274 bias
    for (int idx = tid; idx < 192 * 288; idx += THREADS) {
        int r = idx / 288, k = idx - r * 288;
        float v;
        if (r < 128) {
            int grow = ((r >> 5) << 8) + k0 + (r & 31);
            if      (k < 256)  v = Whh[(grow << 8) + k];
            else if (k < 273)  v = Wih[grow * 18 + (k - 256)];
            else if (k == 274) v = bias[grow];
            else               v = 0.f;
        } else {
            int f = r - 128;
            if      (k < 256)  v = W1[(f << 8) + k];
            else if (k == 274) v = b1[f];
            else               v = 0.f;
        }
        unsigned short lo, hi = bsplit(v, lo);
        *(unsigned short*)(smem + OFF_AH + r * RS + k * 2) = hi;
        if (r < 128)
            *(unsigned short*)(smem + OFF_AL + r * RS + k * 2) = lo;
    }
    // B constant slots 273..287 (274 = bias-one)
    if (tid < 16) {
        for (int k = 273; k < 288; ++k) {
            *(unsigned short*)(smem + OFF_BH + tid * RS + k * 2) =
                (k == 274) ? (unsigned short)0x3F80 : (unsigned short)0;
            *(unsigned short*)(smem + OFF_BL + tid * RS + k * 2) = 0;
        }
    }
    // h0 -> B h-section (full 256)
    {
        int b = tid & 15, jg = tid >> 4;
        const float* hr = h0 + (bg * BG + b) * Hh;
        #pragma unroll
        for (int i = 0; i < 16; ++i) {
            int k = jg + 16 * i;
            unsigned short lo, hi = bsplit(hr[k], lo);
            *(unsigned short*)(smem + OFF_BH + b * RS + k * 2) = hi;
            *(unsigned short*)(smem + OFF_BL + b * RS + k * 2) = lo;
        }
    }
    if (tid < 128) {
        int grow = ((tid >> 5) << 8) + k0 + (tid & 31);
        w17s[tid] = Wih[grow * 18 + 17];
    }
    if (tid < 64) W2f[tid] = W2[tid];
    if (tid == 0) *b2s = b2[0];
    for (int i = tid; i < BG * HCn; i += THREADS) carr[i] = 0.f;
    if (tid < BG) zloc[tid] = 0.f;
    __syncthreads();
    const unsigned tokbase = *toks;

    // GEMM geometry: warp w owns D-tiles (rtA,nt),(rtA+4,nt),(rtF=8+rtA,nt)
    const int w   = tid >> 5, lan = tid & 31;
    const int rtA = w >> 1, nt = w & 1;
    const int lr  = lan >> 2, lk4 = (lan & 3) * 4;   // k-pair byte offset
    const char* pBH = smem + OFF_BH + (nt * 8 + lr) * RS;
    const char* pBL = smem + OFF_BL + (nt * 8 + lr) * RS;
    const char* ahA = smem + OFF_AH + (rtA * 16 + lr) * RS;
    const char* ahB = ahA + 64 * RS;
    const char* ahF = ahA + 128 * RS;
    const char* alA = smem + OFF_AL + (rtA * 16 + lr) * RS;
    const char* alB = alA + 64 * RS;

    const int gb = tid >> 4, jp = tid & 15, j0 = 2 * jp;   // gates/z lanes
    const int fb = tid & 15, fjg = tid >> 4;               // fill lanes

    // ---- time loop (t == Tt is the z-epilogue, hc0 only) -----------------
    for (int t = 0; t <= Tt; ++t) {
        if (t == Tt && hc != 0) break;
        const int pbuf = (t - 1) & 1;
        const int cbuf = t & 1;

        if (t > 0) {
            wait_peers(bg, hc, tokbase + t);
            // peer h fill: 7 peers x 2 j per thread, coalesced LDG
            #pragma unroll
            for (int pc = 1; pc < 8; ++pc) {
                int cc = (hc + pc) & 7;
                const unsigned* src = &g_hpub[pbuf][bg][cc][0];
                unsigned v0 = __ldcg(src + tid);
                unsigned v1 = __ldcg(src + 256 + tid);
                int kA = 32 * cc + fjg, kB = kA + 16;
                *(unsigned short*)(smem + OFF_BH + fb * RS + kA * 2) = (unsigned short)(v0 & 0xffffu);
                *(unsigned short*)(smem + OFF_BL + fb * RS + kA * 2) = (unsigned short)(v0 >> 16);
                *(unsigned short*)(smem + OFF_BH + fb * RS + kB * 2) = (unsigned short)(v1 & 0xffffu);
                *(unsigned short*)(smem + OFF_BL + fb * RS + kB * 2) = (unsigned short)(v1 >> 16);
            }
        }
        if (t < Tt) {
            // S_in: slot 256 = z_t, 257..271 = x0..14, 272 = x15
            int b = tid & 15, s = tid >> 4;
            int bglob = bg * BG + b;
            const float* xr = xin + (bglob * Tt + t) * Fd;
            float v = (s == 0) ? zin[bglob * Tt + t] : xr[s - 1];
            unsigned short lo, hi = bsplit(v, lo);
            *(unsigned short*)(smem + OFF_BH + b * RS + (256 + s) * 2) = hi;
            *(unsigned short*)(smem + OFF_BL + b * RS + (256 + s) * 2) = lo;
            if (s == 0) {
                unsigned short lo2, hi2 = bsplit(xr[15], lo2);
                *(unsigned short*)(smem + OFF_BH + b * RS + 272 * 2) = hi2;
                *(unsigned short*)(smem + OFF_BL + b * RS + 272 * 2) = lo2;
            }
        }
        __syncthreads();

        // ---- unified GEMM ------------------------------------------------
        {
            float dA0=0,dA1=0,dA2=0,dA3=0;
            float dB0=0,dB1=0,dB2=0,dB3=0;
            float dF0=0,dF1=0,dF2=0,dF3=0;
            if (t < Tt) {
                #pragma unroll 2
                for (int c = 0; c < NCH; ++c) {
                    const int o = c * 32 + lk4;
                    unsigned B0 = *(const unsigned*)(pBH + o);
                    unsigned B1 = *(const unsigned*)(pBH + o + 16);
                    unsigned C0 = *(const unsigned*)(pBL + o);
                    unsigned C1 = *(const unsigned*)(pBL + o + 16);
                    unsigned a0, a1, a2, a3;
                    a0 = *(const unsigned*)(ahA + o);      a1 = *(const unsigned*)(ahA + 8*RS + o);
                    a2 = *(const unsigned*)(ahA + o + 16); a3 = *(const unsigned*)(ahA + 8*RS + o + 16);
                    mma16816(dA0,dA1,dA2,dA3, a0,a1,a2,a3, B0,B1);
                    mma16816(dA0,dA1,dA2,dA3, a0,a1,a2,a3, C0,C1);
                    a0 = *(const unsigned*)(alA + o);      a1 = *(const unsigned*)(alA + 8*RS + o);
                    a2 = *(const unsigned*)(alA + o + 16); a3 = *(const unsigned*)(alA + 8*RS + o + 16);
                    mma16816(dA0,dA1,dA2,dA3, a0,a1,a2,a3, B0,B1);
                    a0 = *(const unsigned*)(ahB + o);      a1 = *(const unsigned*)(ahB + 8*RS + o);
                    a2 = *(const unsigned*)(ahB + o + 16); a3 = *(const unsigned*)(ahB + 8*RS + o + 16);
                    mma16816(dB0,dB1,dB2,dB3, a0,a1,a2,a3, B0,B1);
                    mma16816(dB0,dB1,dB2,dB3, a0,a1,a2,a3, C0,C1);
                    a0 = *(const unsigned*)(alB + o);      a1 = *(const unsigned*)(alB + 8*RS + o);
                    a2 = *(const unsigned*)(alB + o + 16); a3 = *(const unsigned*)(alB + 8*RS + o + 16);
                    mma16816(dB0,dB1,dB2,dB3, a0,a1,a2,a3, B0,B1);
                    a0 = *(const unsigned*)(ahF + o);      a1 = *(const unsigned*)(ahF + 8*RS + o);
                    a2 = *(const unsigned*)(ahF + o + 16); a3 = *(const unsigned*)(ahF + 8*RS + o + 16);
                    mma16816(dF0,dF1,dF2,dF3, a0,a1,a2,a3, B0,B1);
                    mma16816(dF0,dF1,dF2,dF3, a0,a1,a2,a3, C0,C1);
                }
            } else {
                #pragma unroll 2
                for (int c = 0; c < NCH; ++c) {
                    const int o = c * 32 + lk4;
                    unsigned B0 = *(const unsigned*)(pBH + o);
                    unsigned B1 = *(const unsigned*)(pBH + o + 16);
                    unsigned C0 = *(const unsigned*)(pBL + o);
                    unsigned C1 = *(const unsigned*)(pBL + o + 16);
                    unsigned a0 = *(const unsigned*)(ahF + o);
                    unsigned a1 = *(const unsigned*)(ahF + 8*RS + o);
                    unsigned a2 = *(const unsigned*)(ahF + o + 16);
                    unsigned a3 = *(const unsigned*)(ahF + 8*RS + o + 16);
                    mma16816(dF0,dF1,dF2,dF3, a0,a1,a2,a3, B0,B1);
                    mma16816(dF0,dF1,dF2,dF3, a0,a1,a2,a3, C0,C1);
                }
            }
            // store D tiles: gbuf[b][r], d0=(r0,n0) d1=(r0,n0+1) d2=(r0+8,n0) d3=(r0+8,n0+1)
            float* g = (float*)(smem + OFF_G);
            const int bc = nt * 8 + (lan & 3) * 2;
            const int rA0 = rtA * 16 + lr;
            if (t < Tt) {
                g[bc * 196 + rA0]            = dA0;
                g[(bc + 1) * 196 + rA0]      = dA1;
                g[bc * 196 + rA0 + 8]        = dA2;
                g[(bc + 1) * 196 + rA0 + 8]  = dA3;
                g[bc * 196 + rA0 + 64]       = dB0;
                g[(bc + 1) * 196 + rA0 + 64] = dB1;
                g[bc * 196 + rA0 + 72]       = dB2;
                g[(bc + 1) * 196 + rA0 + 72] = dB3;
            }
            g[bc * 196 + rA0 + 128]       = dF0;
            g[(bc + 1) * 196 + rA0 + 128] = dF1;
            g[bc * 196 + rA0 + 136]       = dF2;
            g[(bc + 1) * 196 + rA0 + 136] = dF3;
        }
        __syncthreads();

        // ---- z_{t-1} from FF rows (b1 rode the bias column) --------------
        if (t > 0) {
            const float* g = (const float*)(smem + OFF_G) + gb * 196;
            float s = 0.f;
            #pragma unroll
            for (int i = 0; i < 4; ++i) {
                int f = jp + 16 * i;
                s += fmaxf(g[128 + f], 0.f) * W2f[f];
            }
            s += __shfl_xor_sync(0xffffffffu, s, 1);
            s += __shfl_xor_sync(0xffffffffu, s, 2);
            s += __shfl_xor_sync(0xffffffffu, s, 4);
            s += __shfl_xor_sync(0xffffffffu, s, 8);
            if (jp == 0) {
                float zn = zloc[gb] + fmaxf(s + *b2s, 0.f);
                zloc[gb] = zn;
                if (hc == 0) out[(bg * BG + gb) * Tt + (t - 1)] = zn;
            }
        }
        __syncthreads();
        if (t == Tt) break;

        // ---- gates: fixup z*w17, nonlinearities, own fill, publish -------
        {
            const float* g = (const float*)(smem + OFF_G) + gb * 196;
            float2 Gi = *(const float2*)(g +  0 + j0);
            float2 Gf = *(const float2*)(g + 32 + j0);
            float2 Gg = *(const float2*)(g + 64 + j0);
            float2 Go = *(const float2*)(g + 96 + j0);
            float zp = zloc[gb];
            Gi.x = fmaf(w17s[j0], zp, Gi.x);       Gi.y = fmaf(w17s[j0 + 1], zp, Gi.y);
            Gf.x = fmaf(w17s[32 + j0], zp, Gf.x);  Gf.y = fmaf(w17s[33 + j0], zp, Gf.y);
            Gg.x = fmaf(w17s[64 + j0], zp, Gg.x);  Gg.y = fmaf(w17s[65 + j0], zp, Gg.y);
            Go.x = fmaf(w17s[96 + j0], zp, Go.x);  Go.y = fmaf(w17s[97 + j0], zp, Go.y);
            float2 cc = *(float2*)(carr + gb * 32 + j0);
            float c0 = siga(Gf.x) * cc.x + siga(Gi.x) * tanha(Gg.x);
            float c1 = siga(Gf.y) * cc.y + siga(Gi.y) * tanha(Gg.y);
            float hh0 = siga(Go.x) * tanha(c0);
            float hh1 = siga(Go.y) * tanha(c1);
            *(float2*)(carr + gb * 32 + j0) = make_float2(c0, c1);
            unsigned short lo0, hi0 = bsplit(hh0, lo0);
            unsigned short lo1, hi1 = bsplit(hh1, lo1);
            int k = k0 + j0;
            *(unsigned short*)(smem + OFF_BH + gb * RS + k * 2)       = hi0;
            *(unsigned short*)(smem + OFF_BL + gb * RS + k * 2)       = lo0;
            *(unsigned short*)(smem + OFF_BH + gb * RS + (k + 1) * 2) = hi1;
            *(unsigned short*)(smem + OFF_BL + gb * RS + (k + 1) * 2) = lo1;
            g_hpub[cbuf][bg][hc][j0 * 16 + gb]       = (unsigned)hi0 | ((unsigned)lo0 << 16);
            g_hpub[cbuf][bg][hc][(j0 + 1) * 16 + gb] = (unsigned)hi1 | ((unsigned)lo1 << 16);
            if (t == Tt - 1) {
                int bglob = bg * BG + gb;
                *(float2*)&out[OUT_H + bglob * Hh + k0 + j0] = make_float2(hh0, hh1);
                *(float2*)&out[OUT_C + bglob * Hh + k0 + j0] = make_float2(c0, c1);
            }
        }
        __syncthreads();
        if (tid == 0) st_rel(&g_gflag[bg][hc][0], tokbase + t + 1);
    }
}

extern "C" void kernel_launch(void* const* d_in, const int* in_sizes, int n_in,
                              void* d_out, int out_size) {
    const float* z   = (const float*)d_in[0];
    const float* x   = (const float*)d_in[1];
    const float* h0  = (const float*)d_in[2];
    const float* Wih = (const float*)d_in[3];
    const float* Whh = (const float*)d_in[4];
    const float* b   = (const float*)d_in[5];
    const float* W1  = (const float*)d_in[6];
    const float* b1  = (const float*)d_in[7];
    const float* W2  = (const float*)d_in[8];
    const float* b2  = (const float*)d_in[9];
    float* out = (float*)d_out;

    cudaFuncSetAttribute(lstm_persistent_kernel,
                         cudaFuncAttributeMaxDynamicSharedMemorySize, SMEM_BYTES);
    lstm_persistent_kernel<<<NBLK, THREADS, SMEM_BYTES>>>(
        z, x, h0, Wih, Whh, b, W1, b1, W2, b2, out);
}

// round 15
// speedup vs baseline: 1.2842x; 1.0014x over previous
#include <cuda_runtime.h>
#include <cuda_bf16.h>

// ---------------------------------------------------------------------------
// Persistent-grid LSTM on HMMA (mma.sync.m16n8k16 bf16), 512 threads.
// 128 blocks = 16 batch groups x 8 hidden chunks.
// Unified GEMM per step: D[192x16] = A[192x288] x B[288x16]
//   rows 0..127  gates (Whh|Wih|0|bias), rows 128..191 W1 (|b1) -> FF fused.
// K split across warp pairs (w, w+8): chunks 0..8 / 9..17, parity combine.
// bf16 hi/lo: gates 3-term, FF 2-term. z: in-register finalize merged into
// the gate section. Bounded spins. Only h exchanged between blocks.
// ---------------------------------------------------------------------------

namespace {
constexpr int Bb = 256, Tt = 200, Fd = 16, Hh = 256;
constexpr int NBLK = 128, BG = 16, HCn = 32, FWD = 64;
constexpr int THREADS = 512;
constexpr int NCH = 18;             // K16 chunks (K = 288)
constexpr int HALF = 9;             // chunks per warp half
constexpr int RS  = 592;            // A/B row stride bytes

constexpr int OFF_AH  = 0;          // 192*592 = 113664
constexpr int OFF_AL  = 113664;     // 128*592 =  75776 -> 189440
constexpr int OFF_BH  = 189440;     //             9472 -> 198912
constexpr int OFF_BL  = 198912;     //             9472 -> 208384
constexpr int OFF_G   = 208384;     // 16*784  =  12544 -> 220928
constexpr int OFF_W17 = 220928;     //              512 -> 221440
constexpr int OFF_W2F = 221440;     //              256 -> 221696
constexpr int OFF_CARR= 221696;     //             2048 -> 223744
constexpr int OFF_ZLOC= 223744;     //  16 f32 (pad 64) -> 223808
constexpr int OFF_B2  = 223808;
constexpr int OFF_TOK = 223812;
constexpr int SMEM_BYTES = 223872;

constexpr int OUT_H = Bb * Tt, OUT_C = OUT_H + Bb * Hh;
}

__device__ unsigned g_gflag[16][8][32];
__device__ unsigned g_hpub[2][16][8][HCn * BG];   // idx j*16+b, val hi|lo<<16

__device__ __forceinline__ float tanha(float x) {
    float y; asm("tanh.approx.f32 %0, %1;" : "=f"(y) : "f"(x)); return y;
}
__device__ __forceinline__ float siga(float x) {
    return fmaf(tanha(x * 0.5f), 0.5f, 0.5f);
}
__device__ __forceinline__ unsigned ld_acq(const unsigned* p) {
    unsigned v;
    asm volatile("ld.acquire.gpu.global.u32 %0, [%1];" : "=r"(v) : "l"(p) : "memory");
    return v;
}
__device__ __forceinline__ void st_rel(unsigned* p, unsigned v) {
    asm volatile("st.release.gpu.global.u32 [%0], %1;" :: "l"(p), "r"(v) : "memory");
}
// Bounded spin (~0.4s worst case): protocol failure -> wrong data, not a hang.
__device__ __forceinline__ void wait_peers(int bg, int hc, unsigned need) {
    for (int spin = 0; spin < (1 << 22); ++spin) {
        bool ok = true;
        #pragma unroll
        for (int p = 1; p < 8; ++p)
            ok &= ((int)(ld_acq(&g_gflag[bg][(hc + p) & 7][0]) - need) >= 0);
        if (ok) return;
        __nanosleep(64);
    }
}
__device__ __forceinline__ void mma16816(float& d0, float& d1, float& d2, float& d3,
                                         unsigned a0, unsigned a1, unsigned a2, unsigned a3,
                                         unsigned b0, unsigned b1) {
    asm("mma.sync.aligned.m16n8k16.row.col.f32.bf16.bf16.f32 "
        "{%0,%1,%2,%3}, {%4,%5,%6,%7}, {%8,%9}, {%0,%1,%2,%3};"
        : "+f"(d0), "+f"(d1), "+f"(d2), "+f"(d3)
        : "r"(a0), "r"(a1), "r"(a2), "r"(a3), "r"(b0), "r"(b1));
}
__device__ __forceinline__ unsigned short bsplit(float v, unsigned short& lo) {
    __nv_bfloat16 h = __float2bfloat16(v);
    lo = __bfloat16_as_ushort(__float2bfloat16(v - __bfloat162float(h)));
    return __bfloat16_as_ushort(h);
}

__global__ void __launch_bounds__(THREADS, 1)
lstm_persistent_kernel(const float* __restrict__ zin,  const float* __restrict__ xin,
                       const float* __restrict__ h0,   const float* __restrict__ Wih,
                       const float* __restrict__ Whh,  const float* __restrict__ bias,
                       const float* __restrict__ W1,   const float* __restrict__ b1,
                       const float* __restrict__ W2,   const float* __restrict__ b2,
                       float* __restrict__ out)
{
    extern __shared__ char smem[];
    float* w17s = (float*)(smem + OFF_W17);
    float* W2f  = (float*)(smem + OFF_W2F);
    float* carr = (float*)(smem + OFF_CARR);
    float* zloc = (float*)(smem + OFF_ZLOC);
    float* b2s  = (float*)(smem + OFF_B2);
    unsigned* toks = (unsigned*)(smem + OFF_TOK);

    const int tid = threadIdx.x;
    const int bg  = blockIdx.x >> 3;
    const int hc  = blockIdx.x & 7;
    const int k0  = hc * HCn;

    // ---- prologue --------------------------------------------------------
    if (tid == 0) *toks = g_gflag[bg][hc][0];
    for (int idx = tid; idx < 192 * 288; idx += THREADS) {
        int r = idx / 288, k = idx - r * 288;
        float v;
        if (r < 128) {
            int grow = ((r >> 5) << 8) + k0 + (r & 31);
            if      (k < 256)  v = Whh[(grow << 8) + k];
            else if (k < 273)  v = Wih[grow * 18 + (k - 256)];
            else if (k == 274) v = bias[grow];
            else               v = 0.f;
        } else {
            int f = r - 128;
            if      (k < 256)  v = W1[(f << 8) + k];
            else if (k == 274) v = b1[f];
            else               v = 0.f;
        }
        unsigned short lo, hi = bsplit(v, lo);
        *(unsigned short*)(smem + OFF_AH + r * RS + k * 2) = hi;
        if (r < 128)
            *(unsigned short*)(smem + OFF_AL + r * RS + k * 2) = lo;
    }
    if (tid < 16) {
        for (int k = 273; k < 288; ++k) {
            *(unsigned short*)(smem + OFF_BH + tid * RS + k * 2) =
                (k == 274) ? (unsigned short)0x3F80 : (unsigned short)0;
            *(unsigned short*)(smem + OFF_BL + tid * RS + k * 2) = 0;
        }
    }
    if (tid < 256) {
        int b = tid & 15, jg = tid >> 4;
        const float* hr = h0 + (bg * BG + b) * Hh;
        #pragma unroll
        for (int i = 0; i < 16; ++i) {
            int k = jg + 16 * i;
            unsigned short lo, hi = bsplit(hr[k], lo);
            *(unsigned short*)(smem + OFF_BH + b * RS + k * 2) = hi;
            *(unsigned short*)(smem + OFF_BL + b * RS + k * 2) = lo;
        }
    }
    if (tid < 128) {
        int grow = ((tid >> 5) << 8) + k0 + (tid & 31);
        w17s[tid] = Wih[grow * 18 + 17];
    }
    if (tid < 64) W2f[tid] = W2[tid];
    if (tid == 0) *b2s = b2[0];
    for (int i = tid; i < BG * HCn; i += THREADS) carr[i] = 0.f;
    if (tid < BG) zloc[tid] = 0.f;
    __syncthreads();
    const unsigned tokbase = *toks;

    // GEMM geometry: 16 warps; (w&7) -> D tiles, (w>>3) -> K half
    const int w16 = tid >> 5, lan = tid & 31;
    const int wsub = w16 >> 3, w = w16 & 7;
    const int rtA = w >> 1, nt = w & 1;
    const int lr  = lan >> 2, lk4 = (lan & 3) * 4;
    const int c0c = wsub * HALF;
    const char* pBH = smem + OFF_BH + (nt * 8 + lr) * RS;
    const char* pBL = smem + OFF_BL + (nt * 8 + lr) * RS;
    const char* ahA = smem + OFF_AH + (rtA * 16 + lr) * RS;
    const char* ahB = ahA + 64 * RS;
    const char* ahF = ahA + 128 * RS;
    const char* alA = smem + OFF_AL + (rtA * 16 + lr) * RS;
    const char* alB = alA + 64 * RS;

    const int gb = tid >> 4, jp = tid & 15, j0 = 2 * jp;   // gates lanes (tid<256)
    const int fjg = tid >> 4;                              // peer-fill j index

    // ---- time loop (t == Tt is the z-epilogue, hc0 only) -----------------
    for (int t = 0; t <= Tt; ++t) {
        if (t == Tt && hc != 0) break;
        const int pbuf = (t - 1) & 1;
        const int cbuf = t & 1;

        if (t > 0) {
            wait_peers(bg, hc, tokbase + t);
            // peer h fill: 512 threads cover all (j,b); 7 LDG each
            int jg = tid >> 4, b = tid & 15;
            #pragma unroll
            for (int pc = 1; pc < 8; ++pc) {
                int cc = (hc + pc) & 7;
                unsigned v = __ldcg(&g_hpub[pbuf][bg][cc][tid & 511]);
                int k = 32 * cc + jg;
                *(unsigned short*)(smem + OFF_BH + b * RS + k * 2) = (unsigned short)(v & 0xffffu);
                *(unsigned short*)(smem + OFF_BL + b * RS + k * 2) = (unsigned short)(v >> 16);
            }
        }
        if (t < Tt && tid < 256) {
            // S_in: slot 256 = z_t, 257..271 = x0..14, 272 = x15
            int b = tid & 15, s = tid >> 4;
            int bglob = bg * BG + b;
            const float* xr = xin + (bglob * Tt + t) * Fd;
            float v = (s == 0) ? zin[bglob * Tt + t] : xr[s - 1];
            unsigned short lo, hi = bsplit(v, lo);
            *(unsigned short*)(smem + OFF_BH + b * RS + (256 + s) * 2) = hi;
            *(unsigned short*)(smem + OFF_BL + b * RS + (256 + s) * 2) = lo;
            if (s == 0) {
                unsigned short lo2, hi2 = bsplit(xr[15], lo2);
                *(unsigned short*)(smem + OFF_BH + b * RS + 272 * 2) = hi2;
                *(unsigned short*)(smem + OFF_BL + b * RS + 272 * 2) = lo2;
            }
        }
        __syncthreads();

        // ---- K-split GEMM ------------------------------------------------
        float dA0=0,dA1=0,dA2=0,dA3=0;
        float dB0=0,dB1=0,dB2=0,dB3=0;
        float dF0=0,dF1=0,dF2=0,dF3=0;
        if (t < Tt) {
            #pragma unroll
            for (int c = c0c; c < c0c + HALF; ++c) {
                const int o = c * 32 + lk4;
                unsigned B0 = *(const unsigned*)(pBH + o);
                unsigned B1 = *(const unsigned*)(pBH + o + 16);
                unsigned C0 = *(const unsigned*)(pBL + o);
                unsigned C1 = *(const unsigned*)(pBL + o + 16);
                unsigned a0, a1, a2, a3;
                a0 = *(const unsigned*)(ahA + o);      a1 = *(const unsigned*)(ahA + 8*RS + o);
                a2 = *(const unsigned*)(ahA + o + 16); a3 = *(const unsigned*)(ahA + 8*RS + o + 16);
                mma16816(dA0,dA1,dA2,dA3, a0,a1,a2,a3, B0,B1);
                mma16816(dA0,dA1,dA2,dA3, a0,a1,a2,a3, C0,C1);
                a0 = *(const unsigned*)(alA + o);      a1 = *(const unsigned*)(alA + 8*RS + o);
                a2 = *(const unsigned*)(alA + o + 16); a3 = *(const unsigned*)(alA + 8*RS + o + 16);
                mma16816(dA0,dA1,dA2,dA3, a0,a1,a2,a3, B0,B1);
                a0 = *(const unsigned*)(ahB + o);      a1 = *(const unsigned*)(ahB + 8*RS + o);
                a2 = *(const unsigned*)(ahB + o + 16); a3 = *(const unsigned*)(ahB + 8*RS + o + 16);
                mma16816(dB0,dB1,dB2,dB3, a0,a1,a2,a3, B0,B1);
                mma16816(dB0,dB1,dB2,dB3, a0,a1,a2,a3, C0,C1);
                a0 = *(const unsigned*)(alB + o);      a1 = *(const unsigned*)(alB + 8*RS + o);
                a2 = *(const unsigned*)(alB + o + 16); a3 = *(const unsigned*)(alB + 8*RS + o + 16);
                mma16816(dB0,dB1,dB2,dB3, a0,a1,a2,a3, B0,B1);
                a0 = *(const unsigned*)(ahF + o);      a1 = *(const unsigned*)(ahF + 8*RS + o);
                a2 = *(const unsigned*)(ahF + o + 16); a3 = *(const unsigned*)(ahF + 8*RS + o + 16);
                mma16816(dF0,dF1,dF2,dF3, a0,a1,a2,a3, B0,B1);
                mma16816(dF0,dF1,dF2,dF3, a0,a1,a2,a3, C0,C1);
            }
        } else {
            #pragma unroll
            for (int c = c0c; c < c0c + HALF; ++c) {
                const int o = c * 32 + lk4;
                unsigned B0 = *(const unsigned*)(pBH + o);
                unsigned B1 = *(const unsigned*)(pBH + o + 16);
                unsigned C0 = *(const unsigned*)(pBL + o);
                unsigned C1 = *(const unsigned*)(pBL + o + 16);
                unsigned a0 = *(const unsigned*)(ahF + o);
                unsigned a1 = *(const unsigned*)(ahF + 8*RS + o);
                unsigned a2 = *(const unsigned*)(ahF + o + 16);
                unsigned a3 = *(const unsigned*)(ahF + 8*RS + o + 16);
                mma16816(dF0,dF1,dF2,dF3, a0,a1,a2,a3, B0,B1);
                mma16816(dF0,dF1,dF2,dF3, a0,a1,a2,a3, C0,C1);
            }
        }
        // parity combine: wsub0 stores, wsub1 adds
        {
            float* g = (float*)(smem + OFF_G);
            const int bc = nt * 8 + (lan & 3) * 2;
            const int rA0 = rtA * 16 + lr;
            if (wsub == 0) {
                if (t < Tt) {
                    g[bc * 196 + rA0]            = dA0;
                    g[(bc + 1) * 196 + rA0]      = dA1;
                    g[bc * 196 + rA0 + 8]        = dA2;
                    g[(bc + 1) * 196 + rA0 + 8]  = dA3;
                    g[bc * 196 + rA0 + 64]       = dB0;
                    g[(bc + 1) * 196 + rA0 + 64] = dB1;
                    g[bc * 196 + rA0 + 72]       = dB2;
                    g[(bc + 1) * 196 + rA0 + 72] = dB3;
                }
                g[bc * 196 + rA0 + 128]       = dF0;
                g[(bc + 1) * 196 + rA0 + 128] = dF1;
                g[bc * 196 + rA0 + 136]       = dF2;
                g[(bc + 1) * 196 + rA0 + 136] = dF3;
            }
            __syncthreads();
            if (wsub == 1) {
                if (t < Tt) {
                    g[bc * 196 + rA0]            += dA0;
                    g[(bc + 1) * 196 + rA0]      += dA1;
                    g[bc * 196 + rA0 + 8]        += dA2;
                    g[(bc + 1) * 196 + rA0 + 8]  += dA3;
                    g[bc * 196 + rA0 + 64]       += dB0;
                    g[(bc + 1) * 196 + rA0 + 64] += dB1;
                    g[bc * 196 + rA0 + 72]       += dB2;
                    g[(bc + 1) * 196 + rA0 + 72] += dB3;
                }
                g[bc * 196 + rA0 + 128]       += dF0;
                g[(bc + 1) * 196 + rA0 + 128] += dF1;
                g[bc * 196 + rA0 + 136]       += dF2;
                g[(bc + 1) * 196 + rA0 + 136] += dF3;
            }
            __syncthreads();
        }

        // ---- merged z finalize + gates (tid < 256) -----------------------
        if (tid < 256) {
            const float* g = (const float*)(smem + OFF_G) + gb * 196;
            float zn = 0.f;
            if (t > 0) {
                float s = 0.f;
                #pragma unroll
                for (int i = 0; i < 4; ++i) {
                    int f = jp + 16 * i;
                    s += fmaxf(g[128 + f], 0.f) * W2f[f];
                }
                s += __shfl_xor_sync(0xffffffffu, s, 1);
                s += __shfl_xor_sync(0xffffffffu, s, 2);
                s += __shfl_xor_sync(0xffffffffu, s, 4);
                s += __shfl_xor_sync(0xffffffffu, s, 8);
                float zold = zloc[gb];
                zn = zold + fmaxf(s + *b2s, 0.f);
                __syncwarp();
                if (jp == 0) {
                    zloc[gb] = zn;
                    if (hc == 0) out[(bg * BG + gb) * Tt + (t - 1)] = zn;
                }
            }
            if (t < Tt) {
                float2 Gi = *(const float2*)(g +  0 + j0);
                float2 Gf = *(const float2*)(g + 32 + j0);
                float2 Gg = *(const float2*)(g + 64 + j0);
                float2 Go = *(const float2*)(g + 96 + j0);
                float zp = zn;   // z_{t-1} (0 at t=0)
                Gi.x = fmaf(w17s[j0], zp, Gi.x);       Gi.y = fmaf(w17s[j0 + 1], zp, Gi.y);
                Gf.x = fmaf(w17s[32 + j0], zp, Gf.x);  Gf.y = fmaf(w17s[33 + j0], zp, Gf.y);
                Gg.x = fmaf(w17s[64 + j0], zp, Gg.x);  Gg.y = fmaf(w17s[65 + j0], zp, Gg.y);
                Go.x = fmaf(w17s[96 + j0], zp, Go.x);  Go.y = fmaf(w17s[97 + j0], zp, Go.y);
                float2 cc = *(float2*)(carr + gb * 32 + j0);
                float c0 = siga(Gf.x) * cc.x + siga(Gi.x) * tanha(Gg.x);
                float c1 = siga(Gf.y) * cc.y + siga(Gi.y) * tanha(Gg.y);
                float hh0 = siga(Go.x) * tanha(c0);
                float hh1 = siga(Go.y) * tanha(c1);
                *(float2*)(carr + gb * 32 + j0) = make_float2(c0, c1);
                unsigned short lo0, hi0 = bsplit(hh0, lo0);
                unsigned short lo1, hi1 = bsplit(hh1, lo1);
                int k = k0 + j0;
                *(unsigned short*)(smem + OFF_BH + gb * RS + k * 2)       = hi0;
                *(unsigned short*)(smem + OFF_BL + gb * RS + k * 2)       = lo0;
                *(unsigned short*)(smem + OFF_BH + gb * RS + (k + 1) * 2) = hi1;
                *(unsigned short*)(smem + OFF_BL + gb * RS + (k + 1) * 2) = lo1;
                g_hpub[cbuf][bg][hc][j0 * 16 + gb]       = (unsigned)hi0 | ((unsigned)lo0 << 16);
                g_hpub[cbuf][bg][hc][(j0 + 1) * 16 + gb] = (unsigned)hi1 | ((unsigned)lo1 << 16);
                if (t == Tt - 1) {
                    int bglob = bg * BG + gb;
                    *(float2*)&out[OUT_H + bglob * Hh + k0 + j0] = make_float2(hh0, hh1);
                    *(float2*)&out[OUT_C + bglob * Hh + k0 + j0] = make_float2(c0, c1);
                }
            }
        }
        if (t == Tt) break;
        __syncthreads();
        if (tid == 0) st_rel(&g_gflag[bg][hc][0], tokbase + t + 1);
    }
}

extern "C" void kernel_launch(void* const* d_in, const int* in_sizes, int n_in,
                              void* d_out, int out_size) {
    const float* z   = (const float*)d_in[0];
    const float* x   = (const float*)d_in[1];
    const float* h0  = (const float*)d_in[2];
    const float* Wih = (const float*)d_in[3];
    const float* Whh = (const float*)d_in[4];
    const float* b   = (const float*)d_in[5];
    const float* W1  = (const float*)d_in[6];
    const float* b1  = (const float*)d_in[7];
    const float* W2  = (const float*)d_in[8];
    const float* b2  = (const float*)d_in[9];
    float* out = (float*)d_out;

    cudaFuncSetAttribute(lstm_persistent_kernel,
                         cudaFuncAttributeMaxDynamicSharedMemorySize, SMEM_BYTES);
    lstm_persistent_kernel<<<NBLK, THREADS, SMEM_BYTES>>>(
        z, x, h0, Wih, Whh, b, W1, b1, W2, b2, out);
}

// round 17
// speedup vs baseline: 1.8316x; 1.4262x over previous
#include <cuda_runtime.h>
#include <cuda_bf16.h>

// ---------------------------------------------------------------------------
// Persistent-grid LSTM on HMMA (mma.sync.m16n8k16 bf16), 512 threads.
// 128 blocks = 16 batch groups x 8 hidden chunks.
// Unified GEMM per step: D[192x16] = A[192x288] x B[288x16]
//   rows 0..127  gates (Whh|Wih|0|bias), rows 128..191 W1 (|b1) -> FF fused.
// K split across warp pairs; parity combine. bf16 hi/lo (gates 3-term, FF
// 2-term); z = in-register finalize. Flags polled by 7 LANES ONLY (bounded,
// ~0.1s cap) -- all-thread polling was hammering L2 with 3584 acquires/pass.
// Only h is exchanged between blocks.
// ---------------------------------------------------------------------------

namespace {
constexpr int Bb = 256, Tt = 200, Fd = 16, Hh = 256;
constexpr int NBLK = 128, BG = 16, HCn = 32, FWD = 64;
constexpr int THREADS = 512;
constexpr int NCH = 18;             // K16 chunks (K = 288)
constexpr int HALF = 9;             // chunks per warp half
constexpr int RS  = 592;            // A/B row stride bytes

constexpr int OFF_AH  = 0;          // 192*592 = 113664
constexpr int OFF_AL  = 113664;     // 128*592 =  75776 -> 189440
constexpr int OFF_BH  = 189440;     //             9472 -> 198912
constexpr int OFF_BL  = 198912;     //             9472 -> 208384
constexpr int OFF_G   = 208384;     // 16*784  =  12544 -> 220928
constexpr int OFF_W17 = 220928;     //              512 -> 221440
constexpr int OFF_W2F = 221440;     //              256 -> 221696
constexpr int OFF_CARR= 221696;     //             2048 -> 223744
constexpr int OFF_ZLOC= 223744;     //  16 f32 (pad 64) -> 223808
constexpr int OFF_B2  = 223808;
constexpr int OFF_TOK = 223812;
constexpr int SMEM_BYTES = 223872;

constexpr int OUT_H = Bb * Tt, OUT_C = OUT_H + Bb * Hh;
}

__device__ unsigned g_gflag[16][8][32];
__device__ unsigned g_hpub[2][16][8][HCn * BG];   // idx j*16+b, val hi|lo<<16

__device__ __forceinline__ float tanha(float x) {
    float y; asm("tanh.approx.f32 %0, %1;" : "=f"(y) : "f"(x)); return y;
}
__device__ __forceinline__ float siga(float x) {
    return fmaf(tanha(x * 0.5f), 0.5f, 0.5f);
}
__device__ __forceinline__ unsigned ld_acq(const unsigned* p) {
    unsigned v;
    asm volatile("ld.acquire.gpu.global.u32 %0, [%1];" : "=r"(v) : "l"(p) : "memory");
    return v;
}
__device__ __forceinline__ void st_rel(unsigned* p, unsigned v) {
    asm volatile("st.release.gpu.global.u32 [%0], %1;" :: "l"(p), "r"(v) : "memory");
}
// Lane-p poll of one peer flag; bounded (~0.1s worst case) so any protocol
// failure surfaces as wrong data (rel_err fail), never a container hang.
__device__ __forceinline__ void poll_one(const unsigned* fp, unsigned need) {
    for (int spin = 0; spin < (1 << 20); ++spin) {
        if ((int)(ld_acq(fp) - need) >= 0) return;
        __nanosleep(64);
    }
}
__device__ __forceinline__ void mma16816(float& d0, float& d1, float& d2, float& d3,
                                         unsigned a0, unsigned a1, unsigned a2, unsigned a3,
                                         unsigned b0, unsigned b1) {
    asm("mma.sync.aligned.m16n8k16.row.col.f32.bf16.bf16.f32 "
        "{%0,%1,%2,%3}, {%4,%5,%6,%7}, {%8,%9}, {%0,%1,%2,%3};"
        : "+f"(d0), "+f"(d1), "+f"(d2), "+f"(d3)
        : "r"(a0), "r"(a1), "r"(a2), "r"(a3), "r"(b0), "r"(b1));
}
__device__ __forceinline__ unsigned short bsplit(float v, unsigned short& lo) {
    __nv_bfloat16 h = __float2bfloat16(v);
    lo = __bfloat16_as_ushort(__float2bfloat16(v - __bfloat162float(h)));
    return __bfloat16_as_ushort(h);
}

__global__ void __launch_bounds__(THREADS, 1)
lstm_persistent_kernel(const float* __restrict__ zin,  const float* __restrict__ xin,
                       const float* __restrict__ h0,   const float* __restrict__ Wih,
                       const float* __restrict__ Whh,  const float* __restrict__ bias,
                       const float* __restrict__ W1,   const float* __restrict__ b1,
                       const float* __restrict__ W2,   const float* __restrict__ b2,
                       float* __restrict__ out)
{
    extern __shared__ char smem[];
    float* w17s = (float*)(smem + OFF_W17);
    float* W2f  = (float*)(smem + OFF_W2F);
    float* carr = (float*)(smem + OFF_CARR);
    float* zloc = (float*)(smem + OFF_ZLOC);
    float* b2s  = (float*)(smem + OFF_B2);
    unsigned* toks = (unsigned*)(smem + OFF_TOK);

    const int tid = threadIdx.x;
    const int bg  = blockIdx.x >> 3;
    const int hc  = blockIdx.x & 7;
    const int k0  = hc * HCn;

    // ---- prologue --------------------------------------------------------
    if (tid == 0) *toks = g_gflag[bg][hc][0];
    for (int idx = tid; idx < 192 * 288; idx += THREADS) {
        int r = idx / 288, k = idx - r * 288;
        float v;
        if (r < 128) {
            int grow = ((r >> 5) << 8) + k0 + (r & 31);
            if      (k < 256)  v = Whh[(grow << 8) + k];
            else if (k < 273)  v = Wih[grow * 18 + (k - 256)];
            else if (k == 274) v = bias[grow];
            else               v = 0.f;
        } else {
            int f = r - 128;
            if      (k < 256)  v = W1[(f << 8) + k];
            else if (k == 274) v = b1[f];
            else               v = 0.f;
        }
        unsigned short lo, hi = bsplit(v, lo);
        *(unsigned short*)(smem + OFF_AH + r * RS + k * 2) = hi;
        if (r < 128)
            *(unsigned short*)(smem + OFF_AL + r * RS + k * 2) = lo;
    }
    if (tid < 16) {
        for (int k = 273; k < 288; ++k) {
            *(unsigned short*)(smem + OFF_BH + tid * RS + k * 2) =
                (k == 274) ? (unsigned short)0x3F80 : (unsigned short)0;
            *(unsigned short*)(smem + OFF_BL + tid * RS + k * 2) = 0;
        }
    }
    if (tid < 256) {
        int b = tid & 15, jg = tid >> 4;
        const float* hr = h0 + (bg * BG + b) * Hh;
        #pragma unroll
        for (int i = 0; i < 16; ++i) {
            int k = jg + 16 * i;
            unsigned short lo, hi = bsplit(hr[k], lo);
            *(unsigned short*)(smem + OFF_BH + b * RS + k * 2) = hi;
            *(unsigned short*)(smem + OFF_BL + b * RS + k * 2) = lo;
        }
    }
    if (tid < 128) {
        int grow = ((tid >> 5) << 8) + k0 + (tid & 31);
        w17s[tid] = Wih[grow * 18 + 17];
    }
    if (tid < 64) W2f[tid] = W2[tid];
    if (tid == 0) *b2s = b2[0];
    for (int i = tid; i < BG * HCn; i += THREADS) carr[i] = 0.f;
    if (tid < BG) zloc[tid] = 0.f;
    __syncthreads();
    const unsigned tokbase = *toks;

    // GEMM geometry: 16 warps; (w&7) -> D tiles, (w>>3) -> K half
    const int w16 = tid >> 5, lan = tid & 31;
    const int wsub = w16 >> 3, w = w16 & 7;
    const int rtA = w >> 1, nt = w & 1;
    const int lr  = lan >> 2, lk4 = (lan & 3) * 4;
    const int c0c = wsub * HALF;
    const char* pBH = smem + OFF_BH + (nt * 8 + lr) * RS;
    const char* pBL = smem + OFF_BL + (nt * 8 + lr) * RS;
    const char* ahA = smem + OFF_AH + (rtA * 16 + lr) * RS;
    const char* ahB = ahA + 64 * RS;
    const char* ahF = ahA + 128 * RS;
    const char* alA = smem + OFF_AL + (rtA * 16 + lr) * RS;
    const char* alB = alA + 64 * RS;

    const int gb = tid >> 4, jp = tid & 15, j0 = 2 * jp;   // gates lanes (tid<256)

    // ---- time loop (t == Tt is the z-epilogue, hc0 only) -----------------
    for (int t = 0; t <= Tt; ++t) {
        if (t == Tt && hc != 0) break;
        const int pbuf = (t - 1) & 1;
        const int cbuf = t & 1;

        // S_in first: LDG latency overlaps the flag wait below
        if (t < Tt && tid < 256) {
            int b = tid & 15, s = tid >> 4;
            int bglob = bg * BG + b;
            const float* xr = xin + (bglob * Tt + t) * Fd;
            float v = (s == 0) ? zin[bglob * Tt + t] : xr[s - 1];
            unsigned short lo, hi = bsplit(v, lo);
            *(unsigned short*)(smem + OFF_BH + b * RS + (256 + s) * 2) = hi;
            *(unsigned short*)(smem + OFF_BL + b * RS + (256 + s) * 2) = lo;
            if (s == 0) {
                unsigned short lo2, hi2 = bsplit(xr[15], lo2);
                *(unsigned short*)(smem + OFF_BH + b * RS + 272 * 2) = hi2;
                *(unsigned short*)(smem + OFF_BL + b * RS + 272 * 2) = lo2;
            }
        }

        if (t > 0) {
            // 7-lane flag poll (bounded), then block-wide barrier
            if (tid < 7)
                poll_one(&g_gflag[bg][(hc + 1 + tid) & 7][0], tokbase + t);
            __syncthreads();
            // peer h fill: 512 threads cover all (j,b); 7 coalesced LDG each
            int jg = tid >> 4, b = tid & 15;
            #pragma unroll
            for (int pc = 1; pc < 8; ++pc) {
                int cc = (hc + pc) & 7;
                unsigned v = __ldcg(&g_hpub[pbuf][bg][cc][tid & 511]);
                int k = 32 * cc + jg;
                *(unsigned short*)(smem + OFF_BH + b * RS + k * 2) = (unsigned short)(v & 0xffffu);
                *(unsigned short*)(smem + OFF_BL + b * RS + k * 2) = (unsigned short)(v >> 16);
            }
        }
        __syncthreads();

        // ---- K-split GEMM ------------------------------------------------
        float dA0=0,dA1=0,dA2=0,dA3=0;
        float dB0=0,dB1=0,dB2=0,dB3=0;
        float dF0=0,dF1=0,dF2=0,dF3=0;
        if (t < Tt) {
            #pragma unroll
            for (int c = c0c; c < c0c + HALF; ++c) {
                const int o = c * 32 + lk4;
                unsigned B0 = *(const unsigned*)(pBH + o);
                unsigned B1 = *(const unsigned*)(pBH + o + 16);
                unsigned C0 = *(const unsigned*)(pBL + o);
                unsigned C1 = *(const unsigned*)(pBL + o + 16);
                unsigned a0, a1, a2, a3;
                a0 = *(const unsigned*)(ahA + o);      a1 = *(const unsigned*)(ahA + 8*RS + o);
                a2 = *(const unsigned*)(ahA + o + 16); a3 = *(const unsigned*)(ahA + 8*RS + o + 16);
                mma16816(dA0,dA1,dA2,dA3, a0,a1,a2,a3, B0,B1);
                mma16816(dA0,dA1,dA2,dA3, a0,a1,a2,a3, C0,C1);
                a0 = *(const unsigned*)(alA + o);      a1 = *(const unsigned*)(alA + 8*RS + o);
                a2 = *(const unsigned*)(alA + o + 16); a3 = *(const unsigned*)(alA + 8*RS + o + 16);
                mma16816(dA0,dA1,dA2,dA3, a0,a1,a2,a3, B0,B1);
                a0 = *(const unsigned*)(ahB + o);      a1 = *(const unsigned*)(ahB + 8*RS + o);
                a2 = *(const unsigned*)(ahB + o + 16); a3 = *(const unsigned*)(ahB + 8*RS + o + 16);
                mma16816(dB0,dB1,dB2,dB3, a0,a1,a2,a3, B0,B1);
                mma16816(dB0,dB1,dB2,dB3, a0,a1,a2,a3, C0,C1);
                a0 = *(const unsigned*)(alB + o);      a1 = *(const unsigned*)(alB + 8*RS + o);
                a2 = *(const unsigned*)(alB + o + 16); a3 = *(const unsigned*)(alB + 8*RS + o + 16);
                mma16816(dB0,dB1,dB2,dB3, a0,a1,a2,a3, B0,B1);
                a0 = *(const unsigned*)(ahF + o);      a1 = *(const unsigned*)(ahF + 8*RS + o);
                a2 = *(const unsigned*)(ahF + o + 16); a3 = *(const unsigned*)(ahF + 8*RS + o + 16);
                mma16816(dF0,dF1,dF2,dF3, a0,a1,a2,a3, B0,B1);
                mma16816(dF0,dF1,dF2,dF3, a0,a1,a2,a3, C0,C1);
            }
        } else {
            #pragma unroll
            for (int c = c0c; c < c0c + HALF; ++c) {
                const int o = c * 32 + lk4;
                unsigned B0 = *(const unsigned*)(pBH + o);
                unsigned B1 = *(const unsigned*)(pBH + o + 16);
                unsigned C0 = *(const unsigned*)(pBL + o);
                unsigned C1 = *(const unsigned*)(pBL + o + 16);
                unsigned a0 = *(const unsigned*)(ahF + o);
                unsigned a1 = *(const unsigned*)(ahF + 8*RS + o);
                unsigned a2 = *(const unsigned*)(ahF + o + 16);
                unsigned a3 = *(const unsigned*)(ahF + 8*RS + o + 16);
                mma16816(dF0,dF1,dF2,dF3, a0,a1,a2,a3, B0,B1);
                mma16816(dF0,dF1,dF2,dF3, a0,a1,a2,a3, C0,C1);
            }
        }
        // parity combine: wsub0 stores, wsub1 adds
        {
            float* g = (float*)(smem + OFF_G);
            const int bc = nt * 8 + (lan & 3) * 2;
            const int rA0 = rtA * 16 + lr;
            if (wsub == 0) {
                if (t < Tt) {
                    g[bc * 196 + rA0]            = dA0;
                    g[(bc + 1) * 196 + rA0]      = dA1;
                    g[bc * 196 + rA0 + 8]        = dA2;
                    g[(bc + 1) * 196 + rA0 + 8]  = dA3;
                    g[bc * 196 + rA0 + 64]       = dB0;
                    g[(bc + 1) * 196 + rA0 + 64] = dB1;
                    g[bc * 196 + rA0 + 72]       = dB2;
                    g[(bc + 1) * 196 + rA0 + 72] = dB3;
                }
                g[bc * 196 + rA0 + 128]       = dF0;
                g[(bc + 1) * 196 + rA0 + 128] = dF1;
                g[bc * 196 + rA0 + 136]       = dF2;
                g[(bc + 1) * 196 + rA0 + 136] = dF3;
            }
            __syncthreads();
            if (wsub == 1) {
                if (t < Tt) {
                    g[bc * 196 + rA0]            += dA0;
                    g[(bc + 1) * 196 + rA0]      += dA1;
                    g[bc * 196 + rA0 + 8]        += dA2;
                    g[(bc + 1) * 196 + rA0 + 8]  += dA3;
                    g[bc * 196 + rA0 + 64]       += dB0;
                    g[(bc + 1) * 196 + rA0 + 64] += dB1;
                    g[bc * 196 + rA0 + 72]       += dB2;
                    g[(bc + 1) * 196 + rA0 + 72] += dB3;
                }
                g[bc * 196 + rA0 + 128]       += dF0;
                g[(bc + 1) * 196 + rA0 + 128] += dF1;
                g[bc * 196 + rA0 + 136]       += dF2;
                g[(bc + 1) * 196 + rA0 + 136] += dF3;
            }
            __syncthreads();
        }

        // ---- merged z finalize + gates (tid < 256) -----------------------
        if (tid < 256) {
            const float* g = (const float*)(smem + OFF_G) + gb * 196;
            float zn = 0.f;
            if (t > 0) {
                float s = 0.f;
                #pragma unroll
                for (int i = 0; i < 4; ++i) {
                    int f = jp + 16 * i;
                    s += fmaxf(g[128 + f], 0.f) * W2f[f];
                }
                s += __shfl_xor_sync(0xffffffffu, s, 1);
                s += __shfl_xor_sync(0xffffffffu, s, 2);
                s += __shfl_xor_sync(0xffffffffu, s, 4);
                s += __shfl_xor_sync(0xffffffffu, s, 8);
                float zold = zloc[gb];
                zn = zold + fmaxf(s + *b2s, 0.f);
                __syncwarp();
                if (jp == 0) {
                    zloc[gb] = zn;
                    if (hc == 0) out[(bg * BG + gb) * Tt + (t - 1)] = zn;
                }
            }
            if (t < Tt) {
                float2 Gi = *(const float2*)(g +  0 + j0);
                float2 Gf = *(const float2*)(g + 32 + j0);
                float2 Gg = *(const float2*)(g + 64 + j0);
                float2 Go = *(const float2*)(g + 96 + j0);
                float zp = zn;   // z_{t-1} (0 at t=0)
                Gi.x = fmaf(w17s[j0], zp, Gi.x);       Gi.y = fmaf(w17s[j0 + 1], zp, Gi.y);
                Gf.x = fmaf(w17s[32 + j0], zp, Gf.x);  Gf.y = fmaf(w17s[33 + j0], zp, Gf.y);
                Gg.x = fmaf(w17s[64 + j0], zp, Gg.x);  Gg.y = fmaf(w17s[65 + j0], zp, Gg.y);
                Go.x = fmaf(w17s[96 + j0], zp, Go.x);  Go.y = fmaf(w17s[97 + j0], zp, Go.y);
                float2 cc = *(float2*)(carr + gb * 32 + j0);
                float c0 = siga(Gf.x) * cc.x + siga(Gi.x) * tanha(Gg.x);
                float c1 = siga(Gf.y) * cc.y + siga(Gi.y) * tanha(Gg.y);
                float hh0 = siga(Go.x) * tanha(c0);
                float hh1 = siga(Go.y) * tanha(c1);
                *(float2*)(carr + gb * 32 + j0) = make_float2(c0, c1);
                unsigned short lo0, hi0 = bsplit(hh0, lo0);
                unsigned short lo1, hi1 = bsplit(hh1, lo1);
                int k = k0 + j0;
                *(unsigned short*)(smem + OFF_BH + gb * RS + k * 2)       = hi0;
                *(unsigned short*)(smem + OFF_BL + gb * RS + k * 2)       = lo0;
                *(unsigned short*)(smem + OFF_BH + gb * RS + (k + 1) * 2) = hi1;
                *(unsigned short*)(smem + OFF_BL + gb * RS + (k + 1) * 2) = lo1;
                g_hpub[cbuf][bg][hc][j0 * 16 + gb]       = (unsigned)hi0 | ((unsigned)lo0 << 16);
                g_hpub[cbuf][bg][hc][(j0 + 1) * 16 + gb] = (unsigned)hi1 | ((unsigned)lo1 << 16);
                if (t == Tt - 1) {
                    int bglob = bg * BG + gb;
                    *(float2*)&out[OUT_H + bglob * Hh + k0 + j0] = make_float2(hh0, hh1);
                    *(float2*)&out[OUT_C + bglob * Hh + k0 + j0] = make_float2(c0, c1);
                }
            }
        }
        if (t == Tt) break;
        __syncthreads();
        if (tid == 0) st_rel(&g_gflag[bg][hc][0], tokbase + t + 1);
    }
}

extern "C" void kernel_launch(void* const* d_in, const int* in_sizes, int n_in,
                              void* d_out, int out_size) {
    const float* z   = (const float*)d_in[0];
    const float* x   = (const float*)d_in[1];
    const float* h0  = (const float*)d_in[2];
    const float* Wih = (const float*)d_in[3];
    const float* Whh = (const float*)d_in[4];
    const float* b   = (const float*)d_in[5];
    const float* W1  = (const float*)d_in[6];
    const float* b1  = (const float*)d_in[7];
    const float* W2  = (const float*)d_in[8];
    const float* b2  = (const float*)d_in[9];
    float* out = (float*)d_out;

    cudaFuncSetAttribute(lstm_persistent_kernel,
                         cudaFuncAttributeMaxDynamicSharedMemorySize, SMEM_BYTES);
    lstm_persistent_kernel<<<NBLK, THREADS, SMEM_BYTES>>>(
        z, x, h0, Wih, Whh, b, W1, b1, W2, b2, out);
}